// round 2
// baseline (speedup 1.0000x reference)
#include <cuda_runtime.h>
#include <math.h>

// Problem constants
#define BB     8
#define CC     96
#define NN     3136      // 56*56
#define COUT   192
#define TM     64        // query tile rows
#define TK     64        // key tile rows
#define NTILE  49        // NN / TK
#define QS     68        // smem row stride (floats), 16B-aligned, odd-ish banks
#define WTS    196       // W chunk smem stride

#define SMEM_FLOATS (2*CC*QS + TK*QS)       // Qt + Kt (union yT) + Pt (union Wt)
#define SMEM_BYTES  (SMEM_FLOATS * 4)       // 69632

// Scratch (no allocation allowed in kernel_launch)
__device__ float g_y[BB * COUT * NN];       // pre-BN conv output
__device__ float g_scale[COUT];             // gamma * rstd
__device__ float g_shift[COUT];             // beta - mean * gamma * rstd

// ---------------------------------------------------------------------------
// Kernel 1: fused flash self-attention (q=k=v = tokens of x) + max-relative
//           relu(x - att) + concat + 1x1 conv (+bias) -> g_y
// Grid: (49 tiles, 8 batches), 256 threads. Thread (ty,tx) = (tid>>4, tid&15).
// ---------------------------------------------------------------------------
__global__ __launch_bounds__(256)
void attn_conv_kernel(const float* __restrict__ x,
                      const float* __restrict__ w,
                      const float* __restrict__ bias)
{
    extern __shared__ float sm[];
    float* Qt = sm;               // [CC][QS]  Qt[c][i] = x[b][c][n0+i]
    float* Kt = sm + CC * QS;     // [CC][QS]  Kt[c][j] = x[b][c][k0+j]; later xjT
    float* Pt = sm + 2 * CC * QS; // [TK][QS]  Pt[j][i] = softmax numerators
    float* Wt = Pt;               // [16][WTS] conv weight chunk (reuse)
    float* yT = sm;               // [COUT][QS] staged conv output (reuse Qt+Kt)

    const int tid = threadIdx.x;
    const int ty  = tid >> 4;     // 0..15
    const int tx  = tid & 15;     // 0..15
    const int b   = blockIdx.y;
    const int n0  = blockIdx.x * TM;
    const float* xb = x + (size_t)b * CC * NN;

    // Load Q tile (transposed, coalesced over i)
    for (int idx = tid; idx < CC * TM; idx += 256) {
        int c = idx >> 6, i = idx & 63;
        Qt[c * QS + i] = xb[c * NN + n0 + i];
    }

    float m[4], l[4], accO[4][6];
#pragma unroll
    for (int ii = 0; ii < 4; ii++) {
        m[ii] = -1e30f; l[ii] = 0.f;
#pragma unroll
        for (int k = 0; k < 6; k++) accO[ii][k] = 0.f;
    }

    for (int t = 0; t < NTILE; t++) {
        __syncthreads();  // prior PV (reads Kt, Pt) done before overwrite
        const int k0 = t * TK;
        for (int idx = tid; idx < CC * TK; idx += 256) {
            int c = idx >> 6, j = idx & 63;
            Kt[c * QS + j] = xb[c * NN + k0 + j];
        }
        __syncthreads();

        // S = Q * K^T  (4x4 microtile per thread)
        float s[4][4];
#pragma unroll
        for (int ii = 0; ii < 4; ii++)
#pragma unroll
            for (int jj = 0; jj < 4; jj++) s[ii][jj] = 0.f;

        {
            const float* qp = Qt + ty * 4;
            const float* kp = Kt + tx * 4;
#pragma unroll 4
            for (int c = 0; c < CC; c++) {
                float4 qa = *(const float4*)(qp + c * QS);
                float4 kb = *(const float4*)(kp + c * QS);
                s[0][0] = fmaf(qa.x, kb.x, s[0][0]);
                s[0][1] = fmaf(qa.x, kb.y, s[0][1]);
                s[0][2] = fmaf(qa.x, kb.z, s[0][2]);
                s[0][3] = fmaf(qa.x, kb.w, s[0][3]);
                s[1][0] = fmaf(qa.y, kb.x, s[1][0]);
                s[1][1] = fmaf(qa.y, kb.y, s[1][1]);
                s[1][2] = fmaf(qa.y, kb.z, s[1][2]);
                s[1][3] = fmaf(qa.y, kb.w, s[1][3]);
                s[2][0] = fmaf(qa.z, kb.x, s[2][0]);
                s[2][1] = fmaf(qa.z, kb.y, s[2][1]);
                s[2][2] = fmaf(qa.z, kb.z, s[2][2]);
                s[2][3] = fmaf(qa.z, kb.w, s[2][3]);
                s[3][0] = fmaf(qa.w, kb.x, s[3][0]);
                s[3][1] = fmaf(qa.w, kb.y, s[3][1]);
                s[3][2] = fmaf(qa.w, kb.z, s[3][2]);
                s[3][3] = fmaf(qa.w, kb.w, s[3][3]);
            }
        }

        // Online softmax per row (row group = 16 lanes sharing ty)
#pragma unroll
        for (int ii = 0; ii < 4; ii++) {
            float v = fmaxf(fmaxf(s[ii][0], s[ii][1]), fmaxf(s[ii][2], s[ii][3]));
            v = fmaxf(v, __shfl_xor_sync(0xffffffffu, v, 1));
            v = fmaxf(v, __shfl_xor_sync(0xffffffffu, v, 2));
            v = fmaxf(v, __shfl_xor_sync(0xffffffffu, v, 4));
            v = fmaxf(v, __shfl_xor_sync(0xffffffffu, v, 8));
            float mn    = fmaxf(m[ii], v);
            float scale = __expf(m[ii] - mn);
            float ps = 0.f;
#pragma unroll
            for (int jj = 0; jj < 4; jj++) {
                float p = __expf(s[ii][jj] - mn);
                Pt[(tx * 4 + jj) * QS + ty * 4 + ii] = p;
                ps += p;
            }
            ps += __shfl_xor_sync(0xffffffffu, ps, 1);
            ps += __shfl_xor_sync(0xffffffffu, ps, 2);
            ps += __shfl_xor_sync(0xffffffffu, ps, 4);
            ps += __shfl_xor_sync(0xffffffffu, ps, 8);
            l[ii] = l[ii] * scale + ps;
            m[ii] = mn;
#pragma unroll
            for (int k = 0; k < 6; k++) accO[ii][k] *= scale;
        }
        __syncthreads();

        // O += P * V   (V[j][c] == Kt[c][j]); O cols per thread: c = tx + 16k
#pragma unroll 2
        for (int j = 0; j < TK; j++) {
            float4 p4 = *(const float4*)(Pt + j * QS + ty * 4);
#pragma unroll
            for (int k = 0; k < 6; k++) {
                float vj = Kt[(tx + 16 * k) * QS + j];
                accO[0][k] = fmaf(p4.x, vj, accO[0][k]);
                accO[1][k] = fmaf(p4.y, vj, accO[1][k]);
                accO[2][k] = fmaf(p4.z, vj, accO[2][k]);
                accO[3][k] = fmaf(p4.w, vj, accO[3][k]);
            }
        }
    }

    // Finalize attention, compute xj = relu(x - att) into Kt (as xjT[c][i])
    float inv[4];
#pragma unroll
    for (int ii = 0; ii < 4; ii++) inv[ii] = 1.f / l[ii];

    __syncthreads();  // all PV reads of Kt done
#pragma unroll
    for (int ii = 0; ii < 4; ii++) {
#pragma unroll
        for (int k = 0; k < 6; k++) {
            int c = tx + 16 * k;
            float att = accO[ii][k] * inv[ii];
            float xv  = Qt[c * QS + ty * 4 + ii];
            Kt[c * QS + ty * 4 + ii] = fmaxf(xv - att, 0.f);
        }
    }
    __syncthreads();

    // 1x1 conv: y[i][o] = sum_cc W[o][cc] * cat[cc][i],  cat = [Qt ; xjT]
    // Thread owns rows i = ty*4.., cols o = tx + 16*kk (kk=0..11)
    float accY[4][12];
#pragma unroll
    for (int ii = 0; ii < 4; ii++)
#pragma unroll
        for (int kk = 0; kk < 12; kk++) accY[ii][kk] = 0.f;

    for (int ch = 0; ch < 12; ch++) {          // 12 chunks x 16 input channels
        __syncthreads();
        for (int idx = tid; idx < 16 * COUT; idx += 256) {
            int o = idx >> 4, r = idx & 15;
            Wt[r * WTS + o] = w[o * (2 * CC) + ch * 16 + r];
        }
        __syncthreads();
        const float* src = (ch < 6) ? (Qt + (ch * 16) * QS)
                                    : (Kt + ((ch - 6) * 16) * QS);
#pragma unroll
        for (int r = 0; r < 16; r++) {
            float4 xa = *(const float4*)(src + r * QS + ty * 4);
#pragma unroll
            for (int kk = 0; kk < 12; kk++) {
                float wv = Wt[r * WTS + tx + 16 * kk];
                accY[0][kk] = fmaf(xa.x, wv, accY[0][kk]);
                accY[1][kk] = fmaf(xa.y, wv, accY[1][kk]);
                accY[2][kk] = fmaf(xa.z, wv, accY[2][kk]);
                accY[3][kk] = fmaf(xa.w, wv, accY[3][kk]);
            }
        }
    }

    __syncthreads();  // done reading Qt/Kt; reuse region as yT
#pragma unroll
    for (int ii = 0; ii < 4; ii++) {
#pragma unroll
        for (int kk = 0; kk < 12; kk++) {
            int o = tx + 16 * kk;
            yT[o * QS + ty * 4 + ii] = accY[ii][kk] + bias[o];
        }
    }
    __syncthreads();

    float* yb = g_y + ((size_t)b * COUT) * NN + n0;
    for (int idx = tid; idx < COUT * TM; idx += 256) {
        int o = idx >> 6, i = idx & 63;
        yb[o * NN + i] = yT[o * QS + i];
    }
}

// ---------------------------------------------------------------------------
// Kernel 2: per-channel BN stats (biased var over B*H*W), no atomics.
// ---------------------------------------------------------------------------
__global__ __launch_bounds__(256)
void bn_stats_kernel(const float* __restrict__ gamma,
                     const float* __restrict__ beta)
{
    const int ch = blockIdx.x;
    float s = 0.f, ss = 0.f;
    for (int b = 0; b < BB; b++) {
        const float* p = g_y + ((size_t)b * COUT + ch) * NN;
        for (int i = threadIdx.x; i < NN; i += 256) {
            float v = p[i];
            s += v; ss += v * v;
        }
    }
    __shared__ float rs[256], rss[256];
    rs[threadIdx.x] = s; rss[threadIdx.x] = ss;
    __syncthreads();
    for (int o = 128; o > 0; o >>= 1) {
        if (threadIdx.x < o) {
            rs[threadIdx.x]  += rs[threadIdx.x + o];
            rss[threadIdx.x] += rss[threadIdx.x + o];
        }
        __syncthreads();
    }
    if (threadIdx.x == 0) {
        const float cnt  = (float)(BB * NN);
        float mean = rs[0] / cnt;
        float var  = rss[0] / cnt - mean * mean;
        float rstd = rsqrtf(var + 1e-5f);
        float a    = gamma[ch] * rstd;
        g_scale[ch] = a;
        g_shift[ch] = beta[ch] - mean * a;
    }
}

// ---------------------------------------------------------------------------
// Kernel 3: normalize + exact GELU (erf via normcdf), vectorized float4.
// ---------------------------------------------------------------------------
__global__ __launch_bounds__(256)
void bn_gelu_kernel(float* __restrict__ out)
{
    const int i4 = blockIdx.x * blockDim.x + threadIdx.x;
    const int total4 = BB * COUT * NN / 4;
    if (i4 >= total4) return;
    const int ch = (i4 / (NN / 4)) % COUT;
    const float a  = g_scale[ch];
    const float sh = g_shift[ch];
    float4 v = ((const float4*)g_y)[i4];
    v.x = v.x * a + sh;  v.x = v.x * normcdff(v.x);
    v.y = v.y * a + sh;  v.y = v.y * normcdff(v.y);
    v.z = v.z * a + sh;  v.z = v.z * normcdff(v.z);
    v.w = v.w * a + sh;  v.w = v.w * normcdff(v.w);
    ((float4*)out)[i4] = v;
}

// ---------------------------------------------------------------------------
extern "C" void kernel_launch(void* const* d_in, const int* in_sizes, int n_in,
                              void* d_out, int out_size)
{
    const float* x     = (const float*)d_in[0];
    const float* w     = (const float*)d_in[1];
    const float* cbias = (const float*)d_in[2];
    const float* gamma = (const float*)d_in[3];
    const float* beta  = (const float*)d_in[4];
    float* out = (float*)d_out;

    cudaFuncSetAttribute(attn_conv_kernel,
                         cudaFuncAttributeMaxDynamicSharedMemorySize, SMEM_BYTES);

    attn_conv_kernel<<<dim3(NTILE, BB), 256, SMEM_BYTES>>>(x, w, cbias);
    bn_stats_kernel<<<COUT, 256>>>(gamma, beta);
    bn_gelu_kernel<<<(BB * COUT * NN / 4 + 255) / 256, 256>>>(out);
}

// round 4
// speedup vs baseline: 2.5317x; 2.5317x over previous
#include <cuda_runtime.h>
#include <cuda_bf16.h>
#include <math.h>
#include <stdint.h>

// ---------------- problem constants ----------------
#define BB     8
#define CC     96
#define NN     3136
#define COUT   192
#define TK     64
#define NTILE  49          // NN / TK
#define QTM    128
#define QTILES 25          // last tile: 64 valid rows

// ---------------- scratch ----------------
__device__ alignas(16) __nv_bfloat16 g_xhi[BB * CC * NN];
__device__ alignas(16) __nv_bfloat16 g_xlo[BB * CC * NN];
__device__ float g_norm[BB * NN];
__device__ int   g_maxn[BB];                 // bits of max norm (nonneg float)
__device__ float g_att[BB * CC * NN];
__device__ float g_y[BB * COUT * NN];
__device__ float g_scale[COUT];
__device__ float g_shift[COUT];

// ---------------- attention smem layout (byte offsets) ----------------
// Qhi [96][128] bf16 (row 256B), Qlo; K/V stages: [96][64] bf16 hi+lo per stage
#define OFF_QHI 0
#define OFF_QLO 24576
#define OFF_K   49152
#define KSTAGE  24576            // hi (12288) + lo (12288)
#define ATT_SMEM (OFF_K + 2 * KSTAGE)   // 98304

// ---------------- PTX helpers ----------------
__device__ __forceinline__ uint32_t smem_u32(const void* p) {
    uint32_t a;
    asm("{ .reg .u64 t; cvta.to.shared.u64 t, %1; cvt.u32.u64 %0, t; }" : "=r"(a) : "l"(p));
    return a;
}
// swizzle for 256-byte rows (Q): xor 16B-chunk bits[4:6] with row bits[8:10]
__device__ __forceinline__ uint32_t swq(uint32_t o) { return o ^ ((o >> 4) & 0x70); }
// swizzle for 128-byte rows (K/V): xor bits[4:6] with row bits[7:9]
__device__ __forceinline__ uint32_t swk(uint32_t o) { return o ^ ((o >> 3) & 0x70); }

__device__ __forceinline__ void ldsm4(uint32_t* r, uint32_t a) {
    asm volatile("ldmatrix.sync.aligned.m8n8.x4.shared.b16 {%0,%1,%2,%3}, [%4];"
                 : "=r"(r[0]), "=r"(r[1]), "=r"(r[2]), "=r"(r[3]) : "r"(a));
}
__device__ __forceinline__ void ldsm4t(uint32_t* r, uint32_t a) {
    asm volatile("ldmatrix.sync.aligned.m8n8.x4.trans.shared.b16 {%0,%1,%2,%3}, [%4];"
                 : "=r"(r[0]), "=r"(r[1]), "=r"(r[2]), "=r"(r[3]) : "r"(a));
}
__device__ __forceinline__ void mma16816(float* d, const uint32_t* a,
                                         uint32_t b0, uint32_t b1) {
    asm volatile(
        "mma.sync.aligned.m16n8k16.row.col.f32.bf16.bf16.f32 "
        "{%0,%1,%2,%3}, {%4,%5,%6,%7}, {%8,%9}, {%0,%1,%2,%3};"
        : "+f"(d[0]), "+f"(d[1]), "+f"(d[2]), "+f"(d[3])
        : "r"(a[0]), "r"(a[1]), "r"(a[2]), "r"(a[3]), "r"(b0), "r"(b1));
}
__device__ __forceinline__ void cpasync16(uint32_t dst, const void* src) {
    asm volatile("cp.async.cg.shared.global [%0], [%1], 16;" :: "r"(dst), "l"(src));
}
#define CP_COMMIT() asm volatile("cp.async.commit_group;" ::: "memory")

// split two fp32 into packed bf16 hi / lo residual pairs (elem0 in low half)
__device__ __forceinline__ void split2(float a, float b, uint32_t& hi, uint32_t& lo) {
    __nv_bfloat16 ah = __float2bfloat16(a), bh = __float2bfloat16(b);
    __nv_bfloat16 al = __float2bfloat16(a - __bfloat162float(ah));
    __nv_bfloat16 bl = __float2bfloat16(b - __bfloat162float(bh));
    hi = (uint32_t)__bfloat16_as_ushort(ah) | ((uint32_t)__bfloat16_as_ushort(bh) << 16);
    lo = (uint32_t)__bfloat16_as_ushort(al) | ((uint32_t)__bfloat16_as_ushort(bl) << 16);
}

// ---------------------------------------------------------------------------
// Kernel 0: split x into bf16 hi/lo, per-token norm, per-batch max norm.
// ---------------------------------------------------------------------------
__global__ __launch_bounds__(256)
void prep_kernel(const float* __restrict__ x)
{
    const int b = blockIdx.y;
    const int n = blockIdx.x * 256 + threadIdx.x;
    if (n >= NN) return;
    const float* xb = x + (size_t)b * CC * NN;
    __nv_bfloat16* hb = g_xhi + (size_t)b * CC * NN;
    __nv_bfloat16* lb = g_xlo + (size_t)b * CC * NN;
    float s = 0.f;
    for (int c = 0; c < CC; c++) {
        float v = xb[c * NN + n];
        __nv_bfloat16 h = __float2bfloat16(v);
        hb[c * NN + n] = h;
        lb[c * NN + n] = __float2bfloat16(v - __bfloat162float(h));
        s = fmaf(v, v, s);
    }
    float norm = sqrtf(s);
    g_norm[b * NN + n] = norm;
    atomicMax(&g_maxn[b], __float_as_int(norm));
}

// ---------------------------------------------------------------------------
// Kernel 1: warp-MMA bf16-split flash attention, static softmax bound.
// Grid (25, 8) x 256 threads (8 warps; warp w owns query rows w*16..w*16+15).
// ---------------------------------------------------------------------------
__global__ __launch_bounds__(256)
void attn_kernel()
{
    extern __shared__ char smc[];
    const uint32_t sb = smem_u32(smc);
    const int tid  = threadIdx.x;
    const int lane = tid & 31, warp = tid >> 5;
    const int b  = blockIdx.y;
    const int n0 = blockIdx.x * QTM;
    const int valid = (NN - n0 < QTM) ? (NN - n0) : QTM;
    const __nv_bfloat16* xh = g_xhi + (size_t)b * CC * NN;
    const __nv_bfloat16* xl = g_xlo + (size_t)b * CC * NN;

    // --- issue Q + K tile 0 loads (group 0) ---
    for (int i = tid; i < CC * 16; i += 256) {     // Q: 96 rows x 16 chunks
        int c = i >> 4, ck = i & 15;
        int q0 = ck * 8;
        int qs = (q0 >= valid) ? q0 - 64 : q0;     // clamp for last tile
        uint32_t d = swq((uint32_t)(c * 256 + ck * 16));
        cpasync16(sb + OFF_QHI + d, xh + c * NN + n0 + qs);
        cpasync16(sb + OFF_QLO + d, xl + c * NN + n0 + qs);
    }
    for (int i = tid; i < CC * 8; i += 256) {      // K0: 96 rows x 8 chunks
        int c = i >> 3, ck = i & 7;
        uint32_t d = swk((uint32_t)(c * 128 + ck * 16));
        cpasync16(sb + OFF_K + d,         xh + c * NN + ck * 8);
        cpasync16(sb + OFF_K + 12288 + d, xl + c * NN + ck * 8);
    }
    CP_COMMIT();

    // per-thread row constants (2 rows per lane)
    const float mnorm = __int_as_float(g_maxn[b]);
    int q0g = warp * 16 + (lane >> 2);
    int q1g = q0g + 8;
    int q0c = (q0g >= valid) ? q0g - 64 : q0g;
    int q1c = (q1g >= valid) ? q1g - 64 : q1g;
    const float mi0 = g_norm[b * NN + n0 + q0c] * mnorm;
    const float mi1 = g_norm[b * NN + n0 + q1c] * mnorm;

    float oacc[12][4];
#pragma unroll
    for (int f = 0; f < 12; f++)
#pragma unroll
        for (int e = 0; e < 4; e++) oacc[f][e] = 0.f;
    float l0 = 0.f, l1 = 0.f;

    uint32_t qah[6][4], qal[6][4];
    const int g  = lane >> 3;
    const int lr = lane & 7;

#pragma unroll 1
    for (int t = 0; t < NTILE; t++) {
        __syncthreads();   // all warps done with buffer (t+1)&1 from tile t-1
        if (t + 1 < NTILE) {
            const int k0 = (t + 1) * TK;
            const uint32_t bs = sb + OFF_K + (uint32_t)((t + 1) & 1) * KSTAGE;
            for (int i = tid; i < CC * 8; i += 256) {
                int c = i >> 3, ck = i & 7;
                uint32_t d = swk((uint32_t)(c * 128 + ck * 16));
                cpasync16(bs + d,         xh + c * NN + k0 + ck * 8);
                cpasync16(bs + 12288 + d, xl + c * NN + k0 + ck * 8);
            }
            CP_COMMIT();
            asm volatile("cp.async.wait_group 1;" ::: "memory");
        } else {
            asm volatile("cp.async.wait_group 0;" ::: "memory");
        }
        __syncthreads();

        if (t == 0) {  // load Q A-fragments once (Q smem is stable afterwards)
#pragma unroll
            for (int k = 0; k < 6; k++) {
                int ch = 16 * k + ((g >= 2) ? 8 : 0) + lr;
                int q  = warp * 16 + ((g & 1) ? 8 : 0);
                uint32_t d = swq((uint32_t)(ch * 256 + q * 2));
                ldsm4t(qah[k], sb + OFF_QHI + d);
                ldsm4t(qal[k], sb + OFF_QLO + d);
            }
        }

        const uint32_t kb = sb + OFF_K + (uint32_t)(t & 1) * KSTAGE;

        // ---- S = Q K^T ----
        float sacc[8][4];
#pragma unroll
        for (int f = 0; f < 8; f++)
#pragma unroll
            for (int e = 0; e < 4; e++) sacc[f][e] = 0.f;

#pragma unroll
        for (int k = 0; k < 6; k++) {
#pragma unroll
            for (int jp = 0; jp < 4; jp++) {
                int ch  = 16 * k + (g & 1) * 8 + lr;
                int key = 16 * jp + (g >> 1) * 8;
                uint32_t d = swk((uint32_t)(ch * 128 + key * 2));
                uint32_t bh[4], bl[4];
                ldsm4t(bh, kb + d);
                ldsm4t(bl, kb + 12288 + d);
                mma16816(sacc[2 * jp],     qah[k], bh[0], bh[1]);
                mma16816(sacc[2 * jp],     qah[k], bl[0], bl[1]);
                mma16816(sacc[2 * jp],     qal[k], bh[0], bh[1]);
                mma16816(sacc[2 * jp + 1], qah[k], bh[2], bh[3]);
                mma16816(sacc[2 * jp + 1], qah[k], bl[2], bl[3]);
                mma16816(sacc[2 * jp + 1], qal[k], bh[2], bh[3]);
            }
        }

        // ---- softmax (thread-local) + pack P to bf16 hi/lo A-fragments ----
        uint32_t pah[4][4], pal[4][4];
#pragma unroll
        for (int jj = 0; jj < 4; jj++) {
            float p0 = __expf(sacc[2 * jj][0] - mi0);
            float p1 = __expf(sacc[2 * jj][1] - mi0);
            float p2 = __expf(sacc[2 * jj][2] - mi1);
            float p3 = __expf(sacc[2 * jj][3] - mi1);
            float p4 = __expf(sacc[2 * jj + 1][0] - mi0);
            float p5 = __expf(sacc[2 * jj + 1][1] - mi0);
            float p6 = __expf(sacc[2 * jj + 1][2] - mi1);
            float p7 = __expf(sacc[2 * jj + 1][3] - mi1);
            l0 += (p0 + p1) + (p4 + p5);
            l1 += (p2 + p3) + (p6 + p7);
            split2(p0, p1, pah[jj][0], pal[jj][0]);
            split2(p2, p3, pah[jj][1], pal[jj][1]);
            split2(p4, p5, pah[jj][2], pal[jj][2]);
            split2(p6, p7, pah[jj][3], pal[jj][3]);
        }

        // ---- O += P V ----
#pragma unroll
        for (int jj = 0; jj < 4; jj++) {
#pragma unroll
            for (int cp = 0; cp < 6; cp++) {
                int ch  = 8 * (2 * cp + (g >> 1)) + lr;
                int key = 16 * jj + (g & 1) * 8;
                uint32_t d = swk((uint32_t)(ch * 128 + key * 2));
                uint32_t bh[4], bl[4];
                ldsm4(bh, kb + d);
                ldsm4(bl, kb + 12288 + d);
                mma16816(oacc[2 * cp],     pah[jj], bh[0], bh[1]);
                mma16816(oacc[2 * cp],     pah[jj], bl[0], bl[1]);
                mma16816(oacc[2 * cp],     pal[jj], bh[0], bh[1]);
                mma16816(oacc[2 * cp + 1], pah[jj], bh[2], bh[3]);
                mma16816(oacc[2 * cp + 1], pah[jj], bl[2], bl[3]);
                mma16816(oacc[2 * cp + 1], pal[jj], bh[2], bh[3]);
            }
        }
    }

    // ---- epilogue: row sums (quad reduce), normalize, write g_att ----
    l0 += __shfl_xor_sync(0xffffffffu, l0, 1);
    l0 += __shfl_xor_sync(0xffffffffu, l0, 2);
    l1 += __shfl_xor_sync(0xffffffffu, l1, 1);
    l1 += __shfl_xor_sync(0xffffffffu, l1, 2);
    const float inv0 = 1.f / l0, inv1 = 1.f / l1;

    float* ab = g_att + (size_t)b * CC * NN + n0;
#pragma unroll
    for (int nf = 0; nf < 12; nf++) {
        int ch = 8 * nf + 2 * (lane & 3);
        if (q0g < valid) {
            ab[ch * NN + q0g]       = oacc[nf][0] * inv0;
            ab[(ch + 1) * NN + q0g] = oacc[nf][1] * inv0;
        }
        if (q1g < valid) {
            ab[ch * NN + q1g]       = oacc[nf][2] * inv1;
            ab[(ch + 1) * NN + q1g] = oacc[nf][3] * inv1;
        }
    }
}

// ---------------------------------------------------------------------------
// Kernel 2: xj = relu(x - att), concat, 1x1 conv (+bias) -> g_y  (SIMT)
// ---------------------------------------------------------------------------
#define CTM 64
#define QS  68
#define WTS 196
#define CONV_SMEM ((2 * CC * QS + CTM * QS) * 4)

__global__ __launch_bounds__(256)
void conv_kernel(const float* __restrict__ x,
                 const float* __restrict__ w,
                 const float* __restrict__ bias)
{
    extern __shared__ float sm[];
    float* Qt = sm;               // x tile  [CC][QS]
    float* Kt = sm + CC * QS;     // xj tile [CC][QS]
    float* Wt = sm + 2 * CC * QS; // [16][WTS]
    float* yT = sm;               // staged output (reuse)

    const int tid = threadIdx.x;
    const int ty = tid >> 4, tx = tid & 15;
    const int b = blockIdx.y;
    const int n0 = blockIdx.x * CTM;
    const float* xb  = x + (size_t)b * CC * NN;
    const float* atb = g_att + (size_t)b * CC * NN;

    for (int idx = tid; idx < CC * CTM; idx += 256) {
        int c = idx >> 6, i = idx & 63;
        float xv = xb[c * NN + n0 + i];
        float av = atb[c * NN + n0 + i];
        Qt[c * QS + i] = xv;
        Kt[c * QS + i] = fmaxf(xv - av, 0.f);
    }

    float accY[4][12];
#pragma unroll
    for (int ii = 0; ii < 4; ii++)
#pragma unroll
        for (int kk = 0; kk < 12; kk++) accY[ii][kk] = 0.f;

    for (int ch = 0; ch < 12; ch++) {
        __syncthreads();
        for (int idx = tid; idx < 16 * COUT; idx += 256) {
            int o = idx >> 4, r = idx & 15;
            Wt[r * WTS + o] = w[o * (2 * CC) + ch * 16 + r];
        }
        __syncthreads();
        const float* src = (ch < 6) ? (Qt + (ch * 16) * QS)
                                    : (Kt + ((ch - 6) * 16) * QS);
#pragma unroll
        for (int r = 0; r < 16; r++) {
            float4 xa = *(const float4*)(src + r * QS + ty * 4);
#pragma unroll
            for (int kk = 0; kk < 12; kk++) {
                float wv = Wt[r * WTS + tx + 16 * kk];
                accY[0][kk] = fmaf(xa.x, wv, accY[0][kk]);
                accY[1][kk] = fmaf(xa.y, wv, accY[1][kk]);
                accY[2][kk] = fmaf(xa.z, wv, accY[2][kk]);
                accY[3][kk] = fmaf(xa.w, wv, accY[3][kk]);
            }
        }
    }

    __syncthreads();
#pragma unroll
    for (int ii = 0; ii < 4; ii++)
#pragma unroll
        for (int kk = 0; kk < 12; kk++) {
            int o = tx + 16 * kk;
            yT[o * QS + ty * 4 + ii] = accY[ii][kk] + bias[o];
        }
    __syncthreads();

    float* yb = g_y + (size_t)b * COUT * NN + n0;
    for (int idx = tid; idx < COUT * CTM; idx += 256) {
        int o = idx >> 6, i = idx & 63;
        yb[o * NN + i] = yT[o * QS + i];
    }
}

// ---------------------------------------------------------------------------
// Kernel 3: BN stats (biased var over B*H*W)
// ---------------------------------------------------------------------------
__global__ __launch_bounds__(256)
void bn_stats_kernel(const float* __restrict__ gamma,
                     const float* __restrict__ beta)
{
    const int ch = blockIdx.x;
    float s = 0.f, ss = 0.f;
    for (int b = 0; b < BB; b++) {
        const float* p = g_y + ((size_t)b * COUT + ch) * NN;
        for (int i = threadIdx.x; i < NN; i += 256) {
            float v = p[i];
            s += v; ss += v * v;
        }
    }
    __shared__ float rs[256], rss[256];
    rs[threadIdx.x] = s; rss[threadIdx.x] = ss;
    __syncthreads();
    for (int o = 128; o > 0; o >>= 1) {
        if (threadIdx.x < o) {
            rs[threadIdx.x]  += rs[threadIdx.x + o];
            rss[threadIdx.x] += rss[threadIdx.x + o];
        }
        __syncthreads();
    }
    if (threadIdx.x == 0) {
        const float cnt = (float)(BB * NN);
        float mean = rs[0] / cnt;
        float var  = rss[0] / cnt - mean * mean;
        float a    = gamma[ch] * rsqrtf(var + 1e-5f);
        g_scale[ch] = a;
        g_shift[ch] = beta[ch] - mean * a;
    }
}

// ---------------------------------------------------------------------------
// Kernel 4: BN apply + exact GELU
// ---------------------------------------------------------------------------
__global__ __launch_bounds__(256)
void bn_gelu_kernel(float* __restrict__ out)
{
    const int i4 = blockIdx.x * blockDim.x + threadIdx.x;
    const int total4 = BB * COUT * NN / 4;
    if (i4 >= total4) return;
    const int ch = (i4 / (NN / 4)) % COUT;
    const float a = g_scale[ch], sh = g_shift[ch];
    float4 v = ((const float4*)g_y)[i4];
    v.x = v.x * a + sh;  v.x = v.x * normcdff(v.x);
    v.y = v.y * a + sh;  v.y = v.y * normcdff(v.y);
    v.z = v.z * a + sh;  v.z = v.z * normcdff(v.z);
    v.w = v.w * a + sh;  v.w = v.w * normcdff(v.w);
    ((float4*)out)[i4] = v;
}

// ---------------------------------------------------------------------------
extern "C" void kernel_launch(void* const* d_in, const int* in_sizes, int n_in,
                              void* d_out, int out_size)
{
    const float* x     = (const float*)d_in[0];
    const float* w     = (const float*)d_in[1];
    const float* cbias = (const float*)d_in[2];
    const float* gamma = (const float*)d_in[3];
    const float* beta  = (const float*)d_in[4];
    float* out = (float*)d_out;

    cudaFuncSetAttribute(attn_kernel, cudaFuncAttributeMaxDynamicSharedMemorySize, ATT_SMEM);
    cudaFuncSetAttribute(conv_kernel, cudaFuncAttributeMaxDynamicSharedMemorySize, CONV_SMEM);

    prep_kernel<<<dim3((NN + 255) / 256, BB), 256>>>(x);
    attn_kernel<<<dim3(QTILES, BB), 256, ATT_SMEM>>>();
    conv_kernel<<<dim3(NTILE, BB), 256, CONV_SMEM>>>(x, w, cbias);
    bn_stats_kernel<<<COUT, 256>>>(gamma, beta);
    bn_gelu_kernel<<<(BB * COUT * NN / 4 + 255) / 256, 256>>>(out);
}

// round 7
// speedup vs baseline: 3.8292x; 1.5125x over previous
#include <cuda_runtime.h>
#include <cuda_bf16.h>
#include <math.h>
#include <stdint.h>

// ---------------- problem constants ----------------
#define BB     8
#define CC     96
#define NN     3136
#define COUT   192
#define TK     64
#define NTILE  49          // NN / TK
#define QTM    64          // query rows per attn block
#define KSPLIT 3

// ---------------- scratch ----------------
__device__ alignas(16) __nv_bfloat16 g_xhi[BB * CC * NN];
__device__ alignas(16) __nv_bfloat16 g_xlo[BB * CC * NN];
__device__ alignas(16) __nv_bfloat16 g_xjhi[BB * CC * NN];
__device__ alignas(16) __nv_bfloat16 g_xjlo[BB * CC * NN];
__device__ alignas(16) __nv_bfloat16 g_whi[COUT * 2 * CC];   // transposed [ch][out]
__device__ alignas(16) __nv_bfloat16 g_wlo[COUT * 2 * CC];
__device__ float g_norm[BB * NN];
__device__ int   g_maxn[BB];
__device__ alignas(16) float g_att[BB * CC * NN];   // O accumulator (atomic)
__device__ alignas(16) float g_l[BB * NN];          // l accumulator (atomic)
__device__ float g_y[BB * COUT * NN];
__device__ float g_sum[COUT];
__device__ float g_sumsq[COUT];
__device__ float g_scale[COUT];
__device__ float g_shift[COUT];

// ---------------- attn smem layout ----------------
#define OFF_QHI 0
#define OFF_QLO 12288
#define OFF_K   24576
#define KSTAGE  24576                   // hi 12288 + lo 12288
#define ATT_SMEM (OFF_K + 2 * KSTAGE)   // 73728

// ---------------- conv smem layout ----------------
#define CV_CAT_HI 0
#define CV_CAT_LO 24576
#define CV_W      49152                 // + stage*12800 ; hi +0, lo +6400
#define CV_SMEM   (CV_W + 2 * 12800)    // 74752 (ysm 49920 reuses front)

// ---------------- PTX helpers ----------------
__device__ __forceinline__ uint32_t smem_u32(const void* p) {
    uint32_t a;
    asm("{ .reg .u64 t; cvta.to.shared.u64 t, %1; cvt.u32.u64 %0, t; }" : "=r"(a) : "l"(p));
    return a;
}
__device__ __forceinline__ uint32_t swk(uint32_t o) { return o ^ ((o >> 3) & 0x70); }

__device__ __forceinline__ void ldsm4(uint32_t* r, uint32_t a) {
    asm volatile("ldmatrix.sync.aligned.m8n8.x4.shared.b16 {%0,%1,%2,%3}, [%4];"
                 : "=r"(r[0]), "=r"(r[1]), "=r"(r[2]), "=r"(r[3]) : "r"(a));
}
__device__ __forceinline__ void ldsm4t(uint32_t* r, uint32_t a) {
    asm volatile("ldmatrix.sync.aligned.m8n8.x4.trans.shared.b16 {%0,%1,%2,%3}, [%4];"
                 : "=r"(r[0]), "=r"(r[1]), "=r"(r[2]), "=r"(r[3]) : "r"(a));
}
__device__ __forceinline__ void mma16816(float* d, const uint32_t* a,
                                         uint32_t b0, uint32_t b1) {
    asm volatile(
        "mma.sync.aligned.m16n8k16.row.col.f32.bf16.bf16.f32 "
        "{%0,%1,%2,%3}, {%4,%5,%6,%7}, {%8,%9}, {%0,%1,%2,%3};"
        : "+f"(d[0]), "+f"(d[1]), "+f"(d[2]), "+f"(d[3])
        : "r"(a[0]), "r"(a[1]), "r"(a[2]), "r"(a[3]), "r"(b0), "r"(b1));
}
__device__ __forceinline__ void cpasync16(uint32_t dst, const void* src) {
    asm volatile("cp.async.cg.shared.global [%0], [%1], 16;" :: "r"(dst), "l"(src));
}
#define CP_COMMIT() asm volatile("cp.async.commit_group;" ::: "memory")
#define CP_WAIT1()  asm volatile("cp.async.wait_group 1;" ::: "memory")
#define CP_WAIT0()  asm volatile("cp.async.wait_group 0;" ::: "memory")

__device__ __forceinline__ void split2(float a, float b, uint32_t& hi, uint32_t& lo) {
    __nv_bfloat16 ah = __float2bfloat16(a), bh = __float2bfloat16(b);
    __nv_bfloat16 al = __float2bfloat16(a - __bfloat162float(ah));
    __nv_bfloat16 bl = __float2bfloat16(b - __bfloat162float(bh));
    hi = (uint32_t)__bfloat16_as_ushort(ah) | ((uint32_t)__bfloat16_as_ushort(bh) << 16);
    lo = (uint32_t)__bfloat16_as_ushort(al) | ((uint32_t)__bfloat16_as_ushort(bl) << 16);
}

// ---------------------------------------------------------------------------
// Kernel 0a: split x -> bf16 hi/lo, token norms, batch max norm, zero O/l accs
// ---------------------------------------------------------------------------
__global__ __launch_bounds__(256)
void prep_kernel(const float* __restrict__ x)
{
    const int b = blockIdx.y;
    const int n = blockIdx.x * 256 + threadIdx.x;
    if (n >= NN) return;
    const float* xb = x + (size_t)b * CC * NN;
    __nv_bfloat16* hb = g_xhi + (size_t)b * CC * NN;
    __nv_bfloat16* lb = g_xlo + (size_t)b * CC * NN;
    float* ob = g_att + (size_t)b * CC * NN;
    float s = 0.f;
    for (int c = 0; c < CC; c++) {
        float v = xb[c * NN + n];
        __nv_bfloat16 h = __float2bfloat16(v);
        hb[c * NN + n] = h;
        lb[c * NN + n] = __float2bfloat16(v - __bfloat162float(h));
        ob[c * NN + n] = 0.f;
        s = fmaf(v, v, s);
    }
    float norm = sqrtf(s);
    g_norm[b * NN + n] = norm;
    g_l[b * NN + n] = 0.f;
    atomicMax(&g_maxn[b], __float_as_int(norm));
}

// ---------------------------------------------------------------------------
// Kernel 0b: split + transpose W, zero BN stat accumulators
// ---------------------------------------------------------------------------
__global__ __launch_bounds__(256)
void wprep_kernel(const float* __restrict__ w)
{
    const int i = blockIdx.x * 256 + threadIdx.x;
    if (i < COUT) { g_sum[i] = 0.f; g_sumsq[i] = 0.f; }
    if (i >= COUT * 2 * CC) return;
    const int o = i / (2 * CC), c = i % (2 * CC);
    float v = w[i];
    __nv_bfloat16 h = __float2bfloat16(v);
    g_whi[c * COUT + o] = h;
    g_wlo[c * COUT + o] = __float2bfloat16(v - __bfloat162float(h));
}

// ---------------------------------------------------------------------------
// Kernel 1: warp-MMA bf16-split flash attention, static bound, split-K atomics
// Grid (49, 8, 3) x 128 threads (4 warps; warp w -> query rows 16w..16w+15).
// ---------------------------------------------------------------------------
__global__ __launch_bounds__(128)
void attn_kernel()
{
    extern __shared__ char smc[];
    const uint32_t sb = smem_u32(smc);
    const int tid = threadIdx.x;
    const int lane = tid & 31, warp = tid >> 5;
    const int b  = blockIdx.y;
    const int n0 = blockIdx.x * QTM;
    const int tb = blockIdx.z * 16;
    const int te = (blockIdx.z == KSPLIT - 1) ? NTILE : tb + 16;
    const __nv_bfloat16* xh = g_xhi + (size_t)b * CC * NN;
    const __nv_bfloat16* xl = g_xlo + (size_t)b * CC * NN;

    // issue Q tile + first K tile (one cp.async group)
    for (int i = tid; i < CC * 8; i += 128) {
        int c = i >> 3, ck = i & 7;
        uint32_t d = swk((uint32_t)(c * 128 + ck * 16));
        cpasync16(sb + OFF_QHI + d, xh + c * NN + n0 + ck * 8);
        cpasync16(sb + OFF_QLO + d, xl + c * NN + n0 + ck * 8);
    }
    {
        const int k0 = tb * TK;
        for (int i = tid; i < CC * 8; i += 128) {
            int c = i >> 3, ck = i & 7;
            uint32_t d = swk((uint32_t)(c * 128 + ck * 16));
            cpasync16(sb + OFF_K + d,         xh + c * NN + k0 + ck * 8);
            cpasync16(sb + OFF_K + 12288 + d, xl + c * NN + k0 + ck * 8);
        }
    }
    CP_COMMIT();

    const float mnorm = __int_as_float(g_maxn[b]);
    const int q0g = warp * 16 + (lane >> 2);
    const int q1g = q0g + 8;
    const float mi0 = g_norm[b * NN + n0 + q0g] * mnorm;
    const float mi1 = g_norm[b * NN + n0 + q1g] * mnorm;

    float oacc[12][4];
#pragma unroll
    for (int f = 0; f < 12; f++)
#pragma unroll
        for (int e = 0; e < 4; e++) oacc[f][e] = 0.f;
    float l0 = 0.f, l1 = 0.f;

    uint32_t qah[6][4], qal[6][4];
    const int g  = lane >> 3;
    const int lr = lane & 7;

#pragma unroll 1
    for (int t = tb; t < te; t++) {
        __syncthreads();
        if (t + 1 < te) {
            const int k0 = (t + 1) * TK;
            const uint32_t bs = sb + OFF_K + (uint32_t)((t + 1 - tb) & 1) * KSTAGE;
            for (int i = tid; i < CC * 8; i += 128) {
                int c = i >> 3, ck = i & 7;
                uint32_t d = swk((uint32_t)(c * 128 + ck * 16));
                cpasync16(bs + d,         xh + c * NN + k0 + ck * 8);
                cpasync16(bs + 12288 + d, xl + c * NN + k0 + ck * 8);
            }
            CP_COMMIT();
            CP_WAIT1();
        } else {
            CP_WAIT0();
        }
        __syncthreads();

        if (t == tb) {  // Q fragments (stable afterwards)
#pragma unroll
            for (int k = 0; k < 6; k++) {
                int ch = 16 * k + ((g >= 2) ? 8 : 0) + lr;
                int q  = warp * 16 + ((g & 1) ? 8 : 0);
                uint32_t d = swk((uint32_t)(ch * 128 + q * 2));
                ldsm4t(qah[k], sb + OFF_QHI + d);
                ldsm4t(qal[k], sb + OFF_QLO + d);
            }
        }

        const uint32_t kb = sb + OFF_K + (uint32_t)((t - tb) & 1) * KSTAGE;

        // ---- S = Q K^T ----
        float sacc[8][4];
#pragma unroll
        for (int f = 0; f < 8; f++)
#pragma unroll
            for (int e = 0; e < 4; e++) sacc[f][e] = 0.f;

#pragma unroll
        for (int k = 0; k < 6; k++) {
#pragma unroll
            for (int jp = 0; jp < 4; jp++) {
                int ch  = 16 * k + (g & 1) * 8 + lr;
                int key = 16 * jp + (g >> 1) * 8;
                uint32_t d = swk((uint32_t)(ch * 128 + key * 2));
                uint32_t bh[4], bl[4];
                ldsm4t(bh, kb + d);
                ldsm4t(bl, kb + 12288 + d);
                mma16816(sacc[2 * jp],     qah[k], bh[0], bh[1]);
                mma16816(sacc[2 * jp],     qah[k], bl[0], bl[1]);
                mma16816(sacc[2 * jp],     qal[k], bh[0], bh[1]);
                mma16816(sacc[2 * jp + 1], qah[k], bh[2], bh[3]);
                mma16816(sacc[2 * jp + 1], qah[k], bl[2], bl[3]);
                mma16816(sacc[2 * jp + 1], qal[k], bh[2], bh[3]);
            }
        }

        // ---- softmax (thread-local) -> P bf16 hi/lo A-frags ----
        uint32_t pah[4][4], pal[4][4];
#pragma unroll
        for (int jj = 0; jj < 4; jj++) {
            float p0 = __expf(sacc[2 * jj][0] - mi0);
            float p1 = __expf(sacc[2 * jj][1] - mi0);
            float p2 = __expf(sacc[2 * jj][2] - mi1);
            float p3 = __expf(sacc[2 * jj][3] - mi1);
            float p4 = __expf(sacc[2 * jj + 1][0] - mi0);
            float p5 = __expf(sacc[2 * jj + 1][1] - mi0);
            float p6 = __expf(sacc[2 * jj + 1][2] - mi1);
            float p7 = __expf(sacc[2 * jj + 1][3] - mi1);
            l0 += (p0 + p1) + (p4 + p5);
            l1 += (p2 + p3) + (p6 + p7);
            split2(p0, p1, pah[jj][0], pal[jj][0]);
            split2(p2, p3, pah[jj][1], pal[jj][1]);
            split2(p4, p5, pah[jj][2], pal[jj][2]);
            split2(p6, p7, pah[jj][3], pal[jj][3]);
        }

        // ---- O += P V ----
#pragma unroll
        for (int jj = 0; jj < 4; jj++) {
#pragma unroll
            for (int cp = 0; cp < 6; cp++) {
                int ch  = 8 * (2 * cp + (g >> 1)) + lr;
                int key = 16 * jj + (g & 1) * 8;
                uint32_t d = swk((uint32_t)(ch * 128 + key * 2));
                uint32_t bh[4], bl[4];
                ldsm4(bh, kb + d);
                ldsm4(bl, kb + 12288 + d);
                mma16816(oacc[2 * cp],     pah[jj], bh[0], bh[1]);
                mma16816(oacc[2 * cp],     pah[jj], bl[0], bl[1]);
                mma16816(oacc[2 * cp],     pal[jj], bh[0], bh[1]);
                mma16816(oacc[2 * cp + 1], pah[jj], bh[2], bh[3]);
                mma16816(oacc[2 * cp + 1], pah[jj], bl[2], bl[3]);
                mma16816(oacc[2 * cp + 1], pal[jj], bh[2], bh[3]);
            }
        }
    }

    // ---- epilogue: accumulate partial O and l ----
    l0 += __shfl_xor_sync(0xffffffffu, l0, 1);
    l0 += __shfl_xor_sync(0xffffffffu, l0, 2);
    l1 += __shfl_xor_sync(0xffffffffu, l1, 1);
    l1 += __shfl_xor_sync(0xffffffffu, l1, 2);

    float* ob = g_att + (size_t)b * CC * NN + n0;
#pragma unroll
    for (int nf = 0; nf < 12; nf++) {
        int c = 8 * nf + 2 * (lane & 3);
        atomicAdd(&ob[c * NN + q0g],       oacc[nf][0]);
        atomicAdd(&ob[(c + 1) * NN + q0g], oacc[nf][1]);
        atomicAdd(&ob[c * NN + q1g],       oacc[nf][2]);
        atomicAdd(&ob[(c + 1) * NN + q1g], oacc[nf][3]);
    }
    if ((lane & 3) == 0) {
        atomicAdd(&g_l[b * NN + n0 + q0g], l0);
        atomicAdd(&g_l[b * NN + n0 + q1g], l1);
    }
}

// ---------------------------------------------------------------------------
// Kernel 2: finalize attention: xj = relu(x - O/l) -> bf16 hi/lo
// ---------------------------------------------------------------------------
__global__ __launch_bounds__(256)
void attn_fin_kernel(const float* __restrict__ x)
{
    const int i4 = blockIdx.x * 256 + threadIdx.x;
    const int per = CC * NN / 4;
    if (i4 >= BB * per) return;
    const int b = i4 / per, r = i4 - b * per;
    const int n4 = r % (NN / 4);
    float4 o  = ((const float4*)g_att)[i4];
    float4 lv = ((const float4*)g_l)[b * (NN / 4) + n4];
    float4 xv = ((const float4*)x)[i4];
    float j0 = fmaxf(xv.x - o.x / lv.x, 0.f);
    float j1 = fmaxf(xv.y - o.y / lv.y, 0.f);
    float j2 = fmaxf(xv.z - o.z / lv.z, 0.f);
    float j3 = fmaxf(xv.w - o.w / lv.w, 0.f);
    uint2 hi, lo;
    split2(j0, j1, hi.x, lo.x);
    split2(j2, j3, hi.y, lo.y);
    ((uint2*)g_xjhi)[i4] = hi;
    ((uint2*)g_xjlo)[i4] = lo;
}

// ---------------------------------------------------------------------------
// Kernel 3: 1x1 conv via bf16-split MMA + bias + fused BN partial stats
// Grid (49, 8) x 256 threads (8 warps: wy=warp>>1 -> 48 out rows, wx -> 32 tok)
// ---------------------------------------------------------------------------
__global__ __launch_bounds__(256)
void conv_kernel(const float* __restrict__ bias)
{
    extern __shared__ char smc[];
    const uint32_t sb = smem_u32(smc);
    const int tid = threadIdx.x;
    const int lane = tid & 31, warp = tid >> 5;
    const int wy = warp >> 1, wx = warp & 1;
    const int b = blockIdx.y, n0 = blockIdx.x * 64;
    const __nv_bfloat16* xh = g_xhi  + (size_t)b * CC * NN;
    const __nv_bfloat16* xl = g_xlo  + (size_t)b * CC * NN;
    const __nv_bfloat16* jh = g_xjhi + (size_t)b * CC * NN;
    const __nv_bfloat16* jl = g_xjlo + (size_t)b * CC * NN;

    // cat tile [192 ch][64 tok] + W chunk 0 (one group)
    for (int i = tid; i < 192 * 8; i += 256) {
        int c = i >> 3, ck = i & 7;
        uint32_t d = swk((uint32_t)(c * 128 + ck * 16));
        const __nv_bfloat16* sh = (c < CC) ? (xh + c * NN) : (jh + (c - CC) * NN);
        const __nv_bfloat16* sl = (c < CC) ? (xl + c * NN) : (jl + (c - CC) * NN);
        cpasync16(sb + CV_CAT_HI + d, sh + n0 + ck * 8);
        cpasync16(sb + CV_CAT_LO + d, sl + n0 + ck * 8);
    }
    for (int i = tid; i < 16 * 24; i += 256) {
        int rr = i / 24, cc = i % 24;
        cpasync16(sb + CV_W + rr * 400 + cc * 16,        g_whi + rr * COUT + cc * 8);
        cpasync16(sb + CV_W + 6400 + rr * 400 + cc * 16, g_wlo + rr * COUT + cc * 8);
    }
    CP_COMMIT();

    float cacc[3][4][4];
#pragma unroll
    for (int m = 0; m < 3; m++)
#pragma unroll
        for (int n = 0; n < 4; n++)
#pragma unroll
            for (int e = 0; e < 4; e++) cacc[m][n][e] = 0.f;

    const int g = lane >> 3, lr = lane & 7;

#pragma unroll 1
    for (int k = 0; k < 12; k++) {
        if (k + 1 < 12) {
            const uint32_t wb = sb + CV_W + (uint32_t)((k + 1) & 1) * 12800;
            const int k0n = (k + 1) * 16;
            for (int i = tid; i < 16 * 24; i += 256) {
                int rr = i / 24, cc = i % 24;
                cpasync16(wb + rr * 400 + cc * 16,        g_whi + (k0n + rr) * COUT + cc * 8);
                cpasync16(wb + 6400 + rr * 400 + cc * 16, g_wlo + (k0n + rr) * COUT + cc * 8);
            }
            CP_COMMIT();
            CP_WAIT1();
        } else {
            CP_WAIT0();
        }
        __syncthreads();

        const uint32_t wb = sb + CV_W + (uint32_t)(k & 1) * 12800;
        uint32_t ah[3][4], al[3][4];
#pragma unroll
        for (int mf = 0; mf < 3; mf++) {
            int out = 48 * wy + 16 * mf + ((g & 1) ? 8 : 0);
            int chh = ((g >= 2) ? 8 : 0) + lr;
            uint32_t d = (uint32_t)(chh * 400 + out * 2);
            ldsm4t(ah[mf], wb + d);
            ldsm4t(al[mf], wb + 6400 + d);
        }
#pragma unroll
        for (int jp = 0; jp < 2; jp++) {
            int ch  = k * 16 + (g & 1) * 8 + lr;
            int key = 32 * wx + 16 * jp + (g >> 1) * 8;
            uint32_t d = swk((uint32_t)(ch * 128 + key * 2));
            uint32_t bh[4], bl[4];
            ldsm4t(bh, sb + CV_CAT_HI + d);
            ldsm4t(bl, sb + CV_CAT_LO + d);
#pragma unroll
            for (int mf = 0; mf < 3; mf++) {
                mma16816(cacc[mf][2 * jp],     ah[mf], bh[0], bh[1]);
                mma16816(cacc[mf][2 * jp],     ah[mf], bl[0], bl[1]);
                mma16816(cacc[mf][2 * jp],     al[mf], bh[0], bh[1]);
                mma16816(cacc[mf][2 * jp + 1], ah[mf], bh[2], bh[3]);
                mma16816(cacc[mf][2 * jp + 1], ah[mf], bl[2], bl[3]);
                mma16816(cacc[mf][2 * jp + 1], al[mf], bh[2], bh[3]);
            }
        }
        __syncthreads();
    }

    // ---- bias, stage y in smem (stride 65 floats) ----
    float* ys = (float*)smc;
#pragma unroll
    for (int mf = 0; mf < 3; mf++) {
        int r0 = 48 * wy + 16 * mf + (lane >> 2);
        float b0 = bias[r0], b1 = bias[r0 + 8];
#pragma unroll
        for (int nf = 0; nf < 4; nf++) {
            int tok = 32 * wx + 8 * nf + 2 * (lane & 3);
            ys[r0 * 65 + tok]           = cacc[mf][nf][0] + b0;
            ys[r0 * 65 + tok + 1]       = cacc[mf][nf][1] + b0;
            ys[(r0 + 8) * 65 + tok]     = cacc[mf][nf][2] + b1;
            ys[(r0 + 8) * 65 + tok + 1] = cacc[mf][nf][3] + b1;
        }
    }
    __syncthreads();

    // ---- partial BN stats ----
    if (tid < COUT) {
        float s = 0.f, ss = 0.f;
#pragma unroll 4
        for (int i = 0; i < 64; i++) {
            float v = ys[tid * 65 + i];
            s += v; ss = fmaf(v, v, ss);
        }
        atomicAdd(&g_sum[tid], s);
        atomicAdd(&g_sumsq[tid], ss);
    }

    // ---- write y (coalesced) ----
    float* yb = g_y + (size_t)b * COUT * NN + n0;
    for (int i = tid; i < COUT * 64; i += 256) {
        int rr = i >> 6, cc = i & 63;
        yb[rr * NN + cc] = ys[rr * 65 + cc];
    }
}

// ---------------------------------------------------------------------------
// Kernel 4: BN scale/shift from accumulated stats
// ---------------------------------------------------------------------------
__global__ void bn_fin_kernel(const float* __restrict__ gamma,
                              const float* __restrict__ beta)
{
    const int c = threadIdx.x;
    if (c >= COUT) return;
    const float cnt = (float)(BB * NN);
    float mean = g_sum[c] / cnt;
    float var  = g_sumsq[c] / cnt - mean * mean;
    float a    = gamma[c] * rsqrtf(var + 1e-5f);
    g_scale[c] = a;
    g_shift[c] = beta[c] - mean * a;
}

// ---------------------------------------------------------------------------
// Kernel 5: BN apply + exact GELU
// ---------------------------------------------------------------------------
__global__ __launch_bounds__(256)
void bn_gelu_kernel(float* __restrict__ out)
{
    const int i4 = blockIdx.x * blockDim.x + threadIdx.x;
    const int total4 = BB * COUT * NN / 4;
    if (i4 >= total4) return;
    const int ch = (i4 / (NN / 4)) % COUT;
    const float a = g_scale[ch], sh = g_shift[ch];
    float4 v = ((const float4*)g_y)[i4];
    v.x = v.x * a + sh;  v.x = v.x * normcdff(v.x);
    v.y = v.y * a + sh;  v.y = v.y * normcdff(v.y);
    v.z = v.z * a + sh;  v.z = v.z * normcdff(v.z);
    v.w = v.w * a + sh;  v.w = v.w * normcdff(v.w);
    ((float4*)out)[i4] = v;
}

// ---------------------------------------------------------------------------
extern "C" void kernel_launch(void* const* d_in, const int* in_sizes, int n_in,
                              void* d_out, int out_size)
{
    const float* x     = (const float*)d_in[0];
    const float* w     = (const float*)d_in[1];
    const float* cbias = (const float*)d_in[2];
    const float* gamma = (const float*)d_in[3];
    const float* beta  = (const float*)d_in[4];
    float* out = (float*)d_out;

    cudaFuncSetAttribute(attn_kernel, cudaFuncAttributeMaxDynamicSharedMemorySize, ATT_SMEM);
    cudaFuncSetAttribute(conv_kernel, cudaFuncAttributeMaxDynamicSharedMemorySize, CV_SMEM);

    prep_kernel<<<dim3((NN + 255) / 256, BB), 256>>>(x);
    wprep_kernel<<<(COUT * 2 * CC + 255) / 256, 256>>>(w);
    attn_kernel<<<dim3(NTILE, BB, KSPLIT), 128, ATT_SMEM>>>();
    attn_fin_kernel<<<(BB * CC * NN / 4 + 255) / 256, 256>>>(x);
    conv_kernel<<<dim3(NTILE, BB), 256, CV_SMEM>>>(cbias);
    bn_fin_kernel<<<1, COUT>>>(gamma, beta);
    bn_gelu_kernel<<<(BB * COUT * NN / 4 + 255) / 256, 256>>>(out);
}

// round 10
// speedup vs baseline: 4.3018x; 1.1234x over previous
#include <cuda_runtime.h>
#include <cuda_fp16.h>
#include <math.h>
#include <stdint.h>

// ---------------- problem constants ----------------
#define BB     8
#define CC     96
#define NN     3136
#define COUT   192
#define TK     64
#define NTILE  49          // NN / TK
#define QTM    64          // query rows per attn block
#define KSPLIT 3

// ---------------- scratch ----------------
__device__ alignas(16) __half g_xhi[BB * CC * NN];
__device__ alignas(16) __half g_xlo[BB * CC * NN];
__device__ alignas(16) __half g_xjhi[BB * CC * NN];
__device__ alignas(16) __half g_xjlo[BB * CC * NN];
__device__ alignas(16) __half g_whi[COUT * 2 * CC];   // transposed [ch][out]
__device__ alignas(16) __half g_wlo[COUT * 2 * CC];
__device__ float g_norm[BB * NN];
__device__ int   g_maxn[BB];
__device__ alignas(16) float g_att[BB * CC * NN];   // O accumulator (atomic)
__device__ alignas(16) float g_l[BB * NN];          // l accumulator (atomic)
__device__ float g_y[BB * COUT * NN];
__device__ float g_sum[COUT];
__device__ float g_sumsq[COUT];
__device__ float g_scale[COUT];
__device__ float g_shift[COUT];

// ---------------- attn smem layout ----------------
#define OFF_QHI 0
#define OFF_QLO 12288
#define OFF_K   24576
#define KSTAGE  24576                   // hi 12288 + lo 12288
#define ATT_SMEM (OFF_K + 2 * KSTAGE)   // 73728

// ---------------- conv smem layout ----------------
#define CV_CAT_HI 0
#define CV_CAT_LO 24576
#define CV_W      49152                 // + stage*12800 ; hi +0, lo +6400
#define CV_SMEM   (CV_W + 2 * 12800)    // 74752 (ysm 49920 reuses front)

// ---------------- PTX helpers ----------------
__device__ __forceinline__ uint32_t smem_u32(const void* p) {
    uint32_t a;
    asm("{ .reg .u64 t; cvta.to.shared.u64 t, %1; cvt.u32.u64 %0, t; }" : "=r"(a) : "l"(p));
    return a;
}
__device__ __forceinline__ uint32_t swk(uint32_t o) { return o ^ ((o >> 3) & 0x70); }

__device__ __forceinline__ void ldsm4(uint32_t* r, uint32_t a) {
    asm volatile("ldmatrix.sync.aligned.m8n8.x4.shared.b16 {%0,%1,%2,%3}, [%4];"
                 : "=r"(r[0]), "=r"(r[1]), "=r"(r[2]), "=r"(r[3]) : "r"(a));
}
__device__ __forceinline__ void ldsm4t(uint32_t* r, uint32_t a) {
    asm volatile("ldmatrix.sync.aligned.m8n8.x4.trans.shared.b16 {%0,%1,%2,%3}, [%4];"
                 : "=r"(r[0]), "=r"(r[1]), "=r"(r[2]), "=r"(r[3]) : "r"(a));
}
__device__ __forceinline__ void mma16816(float* d, const uint32_t* a,
                                         uint32_t b0, uint32_t b1) {
    asm volatile(
        "mma.sync.aligned.m16n8k16.row.col.f32.f16.f16.f32 "
        "{%0,%1,%2,%3}, {%4,%5,%6,%7}, {%8,%9}, {%0,%1,%2,%3};"
        : "+f"(d[0]), "+f"(d[1]), "+f"(d[2]), "+f"(d[3])
        : "r"(a[0]), "r"(a[1]), "r"(a[2]), "r"(a[3]), "r"(b0), "r"(b1));
}
__device__ __forceinline__ void cpasync16(uint32_t dst, const void* src) {
    asm volatile("cp.async.cg.shared.global [%0], [%1], 16;" :: "r"(dst), "l"(src));
}
#define CP_COMMIT() asm volatile("cp.async.commit_group;" ::: "memory")
#define CP_WAIT1()  asm volatile("cp.async.wait_group 1;" ::: "memory")
#define CP_WAIT0()  asm volatile("cp.async.wait_group 0;" ::: "memory")

// pack two floats into fp16x2 (elem0 low half)
__device__ __forceinline__ uint32_t packh2(float a, float b) {
    __half2 h = __floats2half2_rn(a, b);
    return *reinterpret_cast<uint32_t*>(&h);
}
// split two fp32 into fp16 hi + fp16 lo-residual pairs
__device__ __forceinline__ void split2h(float a, float b, uint32_t& hi, uint32_t& lo) {
    __half2 h = __floats2half2_rn(a, b);
    float2 hf = __half22float2(h);
    __half2 l = __floats2half2_rn(a - hf.x, b - hf.y);
    hi = *reinterpret_cast<uint32_t*>(&h);
    lo = *reinterpret_cast<uint32_t*>(&l);
}

// ---------------------------------------------------------------------------
// Kernel 0a: split x -> fp16 hi/lo, token norms, batch max norm, zero O/l accs
// ---------------------------------------------------------------------------
__global__ __launch_bounds__(256)
void prep_kernel(const float* __restrict__ x)
{
    const int b = blockIdx.y;
    const int n = blockIdx.x * 256 + threadIdx.x;
    if (n >= NN) return;
    const float* xb = x + (size_t)b * CC * NN;
    __half* hb = g_xhi + (size_t)b * CC * NN;
    __half* lb = g_xlo + (size_t)b * CC * NN;
    float* ob = g_att + (size_t)b * CC * NN;
    float s = 0.f;
    for (int c = 0; c < CC; c++) {
        float v = xb[c * NN + n];
        __half h = __float2half_rn(v);
        hb[c * NN + n] = h;
        lb[c * NN + n] = __float2half_rn(v - __half2float(h));
        ob[c * NN + n] = 0.f;
        s = fmaf(v, v, s);
    }
    float norm = sqrtf(s);
    g_norm[b * NN + n] = norm;
    g_l[b * NN + n] = 0.f;
    atomicMax(&g_maxn[b], __float_as_int(norm));
}

// ---------------------------------------------------------------------------
// Kernel 0b: split + transpose W, zero BN stat accumulators
// ---------------------------------------------------------------------------
__global__ __launch_bounds__(256)
void wprep_kernel(const float* __restrict__ w)
{
    const int i = blockIdx.x * 256 + threadIdx.x;
    if (i < COUT) { g_sum[i] = 0.f; g_sumsq[i] = 0.f; }
    if (i >= COUT * 2 * CC) return;
    const int o = i / (2 * CC), c = i % (2 * CC);
    float v = w[i];
    __half h = __float2half_rn(v);
    g_whi[c * COUT + o] = h;
    g_wlo[c * COUT + o] = __float2half_rn(v - __half2float(h));
}

// ---------------------------------------------------------------------------
// Kernel 1: warp-MMA fp16-split flash attention with ONLINE per-block softmax
// (fp16 P needs p near 1: static-bound exponents underflow fp16's 6e-8 floor).
// Partial (O,l) rescaled to the static-bound frame in fp32 before atomics.
// Grid (49, 8, 3) x 128 threads (4 warps; warp w -> query rows 16w..16w+15).
// S: 3 products (Qh*Kh + Qh*Kl + Ql*Kh), PV: 2 products (Ph*Vh + Ph*Vl).
// ---------------------------------------------------------------------------
__global__ __launch_bounds__(128)
void attn_kernel()
{
    extern __shared__ char smc[];
    const uint32_t sb = smem_u32(smc);
    const int tid = threadIdx.x;
    const int lane = tid & 31, warp = tid >> 5;
    const int b  = blockIdx.y;
    const int n0 = blockIdx.x * QTM;
    const int tb = blockIdx.z * 16;
    const int te = (blockIdx.z == KSPLIT - 1) ? NTILE : tb + 16;
    const __half* xh = g_xhi + (size_t)b * CC * NN;
    const __half* xl = g_xlo + (size_t)b * CC * NN;

    // issue Q tile + first K tile (one cp.async group)
    for (int i = tid; i < CC * 8; i += 128) {
        int c = i >> 3, ck = i & 7;
        uint32_t d = swk((uint32_t)(c * 128 + ck * 16));
        cpasync16(sb + OFF_QHI + d, xh + c * NN + n0 + ck * 8);
        cpasync16(sb + OFF_QLO + d, xl + c * NN + n0 + ck * 8);
    }
    {
        const int k0 = tb * TK;
        for (int i = tid; i < CC * 8; i += 128) {
            int c = i >> 3, ck = i & 7;
            uint32_t d = swk((uint32_t)(c * 128 + ck * 16));
            cpasync16(sb + OFF_K + d,         xh + c * NN + k0 + ck * 8);
            cpasync16(sb + OFF_K + 12288 + d, xl + c * NN + k0 + ck * 8);
        }
    }
    CP_COMMIT();

    const float mnorm = __int_as_float(g_maxn[b]);
    const int q0g = warp * 16 + (lane >> 2);
    const int q1g = q0g + 8;
    const float mi0 = g_norm[b * NN + n0 + q0g] * mnorm;  // static upper bound
    const float mi1 = g_norm[b * NN + n0 + q1g] * mnorm;

    float oacc[12][4];
#pragma unroll
    for (int f = 0; f < 12; f++)
#pragma unroll
        for (int e = 0; e < 4; e++) oacc[f][e] = 0.f;
    float l0 = 0.f, l1 = 0.f;
    float m0 = -1e30f, m1 = -1e30f;   // running per-block row max

    uint32_t qah[6][4], qal[6][4];
    const int g  = lane >> 3;
    const int lr = lane & 7;

#pragma unroll 1
    for (int t = tb; t < te; t++) {
        __syncthreads();
        if (t + 1 < te) {
            const int k0 = (t + 1) * TK;
            const uint32_t bs = sb + OFF_K + (uint32_t)((t + 1 - tb) & 1) * KSTAGE;
            for (int i = tid; i < CC * 8; i += 128) {
                int c = i >> 3, ck = i & 7;
                uint32_t d = swk((uint32_t)(c * 128 + ck * 16));
                cpasync16(bs + d,         xh + c * NN + k0 + ck * 8);
                cpasync16(bs + 12288 + d, xl + c * NN + k0 + ck * 8);
            }
            CP_COMMIT();
            CP_WAIT1();
        } else {
            CP_WAIT0();
        }
        __syncthreads();

        if (t == tb) {  // Q fragments (stable afterwards)
#pragma unroll
            for (int k = 0; k < 6; k++) {
                int ch = 16 * k + ((g >= 2) ? 8 : 0) + lr;
                int q  = warp * 16 + ((g & 1) ? 8 : 0);
                uint32_t d = swk((uint32_t)(ch * 128 + q * 2));
                ldsm4t(qah[k], sb + OFF_QHI + d);
                ldsm4t(qal[k], sb + OFF_QLO + d);
            }
        }

        const uint32_t kb = sb + OFF_K + (uint32_t)((t - tb) & 1) * KSTAGE;

        // ---- S = Q K^T (3 split products) ----
        float sacc[8][4];
#pragma unroll
        for (int f = 0; f < 8; f++)
#pragma unroll
            for (int e = 0; e < 4; e++) sacc[f][e] = 0.f;

#pragma unroll
        for (int k = 0; k < 6; k++) {
#pragma unroll
            for (int jp = 0; jp < 4; jp++) {
                int ch  = 16 * k + (g & 1) * 8 + lr;
                int key = 16 * jp + (g >> 1) * 8;
                uint32_t d = swk((uint32_t)(ch * 128 + key * 2));
                uint32_t bh[4], bl[4];
                ldsm4t(bh, kb + d);
                ldsm4t(bl, kb + 12288 + d);
                mma16816(sacc[2 * jp],     qah[k], bh[0], bh[1]);
                mma16816(sacc[2 * jp],     qah[k], bl[0], bl[1]);
                mma16816(sacc[2 * jp],     qal[k], bh[0], bh[1]);
                mma16816(sacc[2 * jp + 1], qah[k], bh[2], bh[3]);
                mma16816(sacc[2 * jp + 1], qah[k], bl[2], bl[3]);
                mma16816(sacc[2 * jp + 1], qal[k], bh[2], bh[3]);
            }
        }

        // ---- online row max across this tile's 64 keys (quad reduce) ----
        float mx0 = -1e30f, mx1 = -1e30f;
#pragma unroll
        for (int f = 0; f < 8; f++) {
            mx0 = fmaxf(mx0, fmaxf(sacc[f][0], sacc[f][1]));
            mx1 = fmaxf(mx1, fmaxf(sacc[f][2], sacc[f][3]));
        }
        mx0 = fmaxf(mx0, __shfl_xor_sync(0xffffffffu, mx0, 1));
        mx0 = fmaxf(mx0, __shfl_xor_sync(0xffffffffu, mx0, 2));
        mx1 = fmaxf(mx1, __shfl_xor_sync(0xffffffffu, mx1, 1));
        mx1 = fmaxf(mx1, __shfl_xor_sync(0xffffffffu, mx1, 2));
        const float nm0 = fmaxf(m0, mx0), nm1 = fmaxf(m1, mx1);
        const float sc0 = __expf(m0 - nm0), sc1 = __expf(m1 - nm1);
        m0 = nm0; m1 = nm1;
        l0 *= sc0; l1 *= sc1;
#pragma unroll
        for (int f = 0; f < 12; f++) {
            oacc[f][0] *= sc0; oacc[f][1] *= sc0;
            oacc[f][2] *= sc1; oacc[f][3] *= sc1;
        }

        // ---- softmax (thread-local, p near 1) -> single fp16 P A-frags ----
        uint32_t pah[4][4];
#pragma unroll
        for (int jj = 0; jj < 4; jj++) {
            float p0 = __expf(sacc[2 * jj][0] - m0);
            float p1 = __expf(sacc[2 * jj][1] - m0);
            float p2 = __expf(sacc[2 * jj][2] - m1);
            float p3 = __expf(sacc[2 * jj][3] - m1);
            float p4 = __expf(sacc[2 * jj + 1][0] - m0);
            float p5 = __expf(sacc[2 * jj + 1][1] - m0);
            float p6 = __expf(sacc[2 * jj + 1][2] - m1);
            float p7 = __expf(sacc[2 * jj + 1][3] - m1);
            l0 += (p0 + p1) + (p4 + p5);
            l1 += (p2 + p3) + (p6 + p7);
            pah[jj][0] = packh2(p0, p1);
            pah[jj][1] = packh2(p2, p3);
            pah[jj][2] = packh2(p4, p5);
            pah[jj][3] = packh2(p6, p7);
        }

        // ---- O += P V (2 products: Ph*Vh + Ph*Vl) ----
#pragma unroll
        for (int jj = 0; jj < 4; jj++) {
#pragma unroll
            for (int cp = 0; cp < 6; cp++) {
                int ch  = 8 * (2 * cp + (g >> 1)) + lr;
                int key = 16 * jj + (g & 1) * 8;
                uint32_t d = swk((uint32_t)(ch * 128 + key * 2));
                uint32_t bh[4], bl[4];
                ldsm4(bh, kb + d);
                ldsm4(bl, kb + 12288 + d);
                mma16816(oacc[2 * cp],     pah[jj], bh[0], bh[1]);
                mma16816(oacc[2 * cp],     pah[jj], bl[0], bl[1]);
                mma16816(oacc[2 * cp + 1], pah[jj], bh[2], bh[3]);
                mma16816(oacc[2 * cp + 1], pah[jj], bl[2], bl[3]);
            }
        }
    }

    // ---- epilogue: rescale to global (static-bound) frame in fp32, atomics --
    const float f0 = __expf(m0 - mi0);   // <= 1, fp32 range (same safety as R7)
    const float f1 = __expf(m1 - mi1);

    l0 += __shfl_xor_sync(0xffffffffu, l0, 1);
    l0 += __shfl_xor_sync(0xffffffffu, l0, 2);
    l1 += __shfl_xor_sync(0xffffffffu, l1, 1);
    l1 += __shfl_xor_sync(0xffffffffu, l1, 2);

    float* ob = g_att + (size_t)b * CC * NN + n0;
#pragma unroll
    for (int nf = 0; nf < 12; nf++) {
        int c = 8 * nf + 2 * (lane & 3);
        atomicAdd(&ob[c * NN + q0g],       oacc[nf][0] * f0);
        atomicAdd(&ob[(c + 1) * NN + q0g], oacc[nf][1] * f0);
        atomicAdd(&ob[c * NN + q1g],       oacc[nf][2] * f1);
        atomicAdd(&ob[(c + 1) * NN + q1g], oacc[nf][3] * f1);
    }
    if ((lane & 3) == 0) {
        atomicAdd(&g_l[b * NN + n0 + q0g], l0 * f0);
        atomicAdd(&g_l[b * NN + n0 + q1g], l1 * f1);
    }
}

// ---------------------------------------------------------------------------
// Kernel 2: finalize attention: xj = relu(x - O/l) -> fp16 hi/lo
// ---------------------------------------------------------------------------
__global__ __launch_bounds__(256)
void attn_fin_kernel(const float* __restrict__ x)
{
    const int i4 = blockIdx.x * 256 + threadIdx.x;
    const int per = CC * NN / 4;
    if (i4 >= BB * per) return;
    const int b = i4 / per, r = i4 - b * per;
    const int n4 = r % (NN / 4);
    float4 o  = ((const float4*)g_att)[i4];
    float4 lv = ((const float4*)g_l)[b * (NN / 4) + n4];
    float4 xv = ((const float4*)x)[i4];
    float j0 = fmaxf(xv.x - o.x / lv.x, 0.f);
    float j1 = fmaxf(xv.y - o.y / lv.y, 0.f);
    float j2 = fmaxf(xv.z - o.z / lv.z, 0.f);
    float j3 = fmaxf(xv.w - o.w / lv.w, 0.f);
    uint2 hi, lo;
    split2h(j0, j1, hi.x, lo.x);
    split2h(j2, j3, hi.y, lo.y);
    ((uint2*)g_xjhi)[i4] = hi;
    ((uint2*)g_xjlo)[i4] = lo;
}

// ---------------------------------------------------------------------------
// Kernel 3: 1x1 conv via fp16-split MMA (3 products) + bias + fused BN stats
// Grid (49, 8) x 256 threads (8 warps: wy=warp>>1 -> 48 out rows, wx -> 32 tok)
// ---------------------------------------------------------------------------
__global__ __launch_bounds__(256)
void conv_kernel(const float* __restrict__ bias)
{
    extern __shared__ char smc[];
    const uint32_t sb = smem_u32(smc);
    const int tid = threadIdx.x;
    const int lane = tid & 31, warp = tid >> 5;
    const int wy = warp >> 1, wx = warp & 1;
    const int b = blockIdx.y, n0 = blockIdx.x * 64;
    const __half* xh = g_xhi  + (size_t)b * CC * NN;
    const __half* xl = g_xlo  + (size_t)b * CC * NN;
    const __half* jh = g_xjhi + (size_t)b * CC * NN;
    const __half* jl = g_xjlo + (size_t)b * CC * NN;

    // cat tile [192 ch][64 tok] + W chunk 0 (one group)
    for (int i = tid; i < 192 * 8; i += 256) {
        int c = i >> 3, ck = i & 7;
        uint32_t d = swk((uint32_t)(c * 128 + ck * 16));
        const __half* sh = (c < CC) ? (xh + c * NN) : (jh + (c - CC) * NN);
        const __half* sl = (c < CC) ? (xl + c * NN) : (jl + (c - CC) * NN);
        cpasync16(sb + CV_CAT_HI + d, sh + n0 + ck * 8);
        cpasync16(sb + CV_CAT_LO + d, sl + n0 + ck * 8);
    }
    for (int i = tid; i < 16 * 24; i += 256) {
        int rr = i / 24, cc = i % 24;
        cpasync16(sb + CV_W + rr * 400 + cc * 16,        g_whi + rr * COUT + cc * 8);
        cpasync16(sb + CV_W + 6400 + rr * 400 + cc * 16, g_wlo + rr * COUT + cc * 8);
    }
    CP_COMMIT();

    float cacc[3][4][4];
#pragma unroll
    for (int m = 0; m < 3; m++)
#pragma unroll
        for (int n = 0; n < 4; n++)
#pragma unroll
            for (int e = 0; e < 4; e++) cacc[m][n][e] = 0.f;

    const int g = lane >> 3, lr = lane & 7;

#pragma unroll 1
    for (int k = 0; k < 12; k++) {
        if (k + 1 < 12) {
            const uint32_t wb = sb + CV_W + (uint32_t)((k + 1) & 1) * 12800;
            const int k0n = (k + 1) * 16;
            for (int i = tid; i < 16 * 24; i += 256) {
                int rr = i / 24, cc = i % 24;
                cpasync16(wb + rr * 400 + cc * 16,        g_whi + (k0n + rr) * COUT + cc * 8);
                cpasync16(wb + 6400 + rr * 400 + cc * 16, g_wlo + (k0n + rr) * COUT + cc * 8);
            }
            CP_COMMIT();
            CP_WAIT1();
        } else {
            CP_WAIT0();
        }
        __syncthreads();

        const uint32_t wb = sb + CV_W + (uint32_t)(k & 1) * 12800;
        uint32_t ah[3][4], al[3][4];
#pragma unroll
        for (int mf = 0; mf < 3; mf++) {
            int out = 48 * wy + 16 * mf + ((g & 1) ? 8 : 0);
            int chh = ((g >= 2) ? 8 : 0) + lr;
            uint32_t d = (uint32_t)(chh * 400 + out * 2);
            ldsm4t(ah[mf], wb + d);
            ldsm4t(al[mf], wb + 6400 + d);
        }
#pragma unroll
        for (int jp = 0; jp < 2; jp++) {
            int ch  = k * 16 + (g & 1) * 8 + lr;
            int key = 32 * wx + 16 * jp + (g >> 1) * 8;
            uint32_t d = swk((uint32_t)(ch * 128 + key * 2));
            uint32_t bh[4], bl[4];
            ldsm4t(bh, sb + CV_CAT_HI + d);
            ldsm4t(bl, sb + CV_CAT_LO + d);
#pragma unroll
            for (int mf = 0; mf < 3; mf++) {
                mma16816(cacc[mf][2 * jp],     ah[mf], bh[0], bh[1]);
                mma16816(cacc[mf][2 * jp],     ah[mf], bl[0], bl[1]);
                mma16816(cacc[mf][2 * jp],     al[mf], bh[0], bh[1]);
                mma16816(cacc[mf][2 * jp + 1], ah[mf], bh[2], bh[3]);
                mma16816(cacc[mf][2 * jp + 1], ah[mf], bl[2], bl[3]);
                mma16816(cacc[mf][2 * jp + 1], al[mf], bh[2], bh[3]);
            }
        }
        __syncthreads();
    }

    // ---- bias, stage y in smem (stride 65 floats) ----
    float* ys = (float*)smc;
#pragma unroll
    for (int mf = 0; mf < 3; mf++) {
        int r0 = 48 * wy + 16 * mf + (lane >> 2);
        float b0 = bias[r0], b1 = bias[r0 + 8];
#pragma unroll
        for (int nf = 0; nf < 4; nf++) {
            int tok = 32 * wx + 8 * nf + 2 * (lane & 3);
            ys[r0 * 65 + tok]           = cacc[mf][nf][0] + b0;
            ys[r0 * 65 + tok + 1]       = cacc[mf][nf][1] + b0;
            ys[(r0 + 8) * 65 + tok]     = cacc[mf][nf][2] + b1;
            ys[(r0 + 8) * 65 + tok + 1] = cacc[mf][nf][3] + b1;
        }
    }
    __syncthreads();

    // ---- partial BN stats ----
    if (tid < COUT) {
        float s = 0.f, ss = 0.f;
#pragma unroll 4
        for (int i = 0; i < 64; i++) {
            float v = ys[tid * 65 + i];
            s += v; ss = fmaf(v, v, ss);
        }
        atomicAdd(&g_sum[tid], s);
        atomicAdd(&g_sumsq[tid], ss);
    }

    // ---- write y (coalesced) ----
    float* yb = g_y + (size_t)b * COUT * NN + n0;
    for (int i = tid; i < COUT * 64; i += 256) {
        int rr = i >> 6, cc = i & 63;
        yb[rr * NN + cc] = ys[rr * 65 + cc];
    }
}

// ---------------------------------------------------------------------------
// Kernel 4: BN scale/shift from accumulated stats
// ---------------------------------------------------------------------------
__global__ void bn_fin_kernel(const float* __restrict__ gamma,
                              const float* __restrict__ beta)
{
    const int c = threadIdx.x;
    if (c >= COUT) return;
    const float cnt = (float)(BB * NN);
    float mean = g_sum[c] / cnt;
    float var  = g_sumsq[c] / cnt - mean * mean;
    float a    = gamma[c] * rsqrtf(var + 1e-5f);
    g_scale[c] = a;
    g_shift[c] = beta[c] - mean * a;
}

// ---------------------------------------------------------------------------
// Kernel 5: BN apply + exact GELU
// ---------------------------------------------------------------------------
__global__ __launch_bounds__(256)
void bn_gelu_kernel(float* __restrict__ out)
{
    const int i4 = blockIdx.x * blockDim.x + threadIdx.x;
    const int total4 = BB * COUT * NN / 4;
    if (i4 >= total4) return;
    const int ch = (i4 / (NN / 4)) % COUT;
    const float a = g_scale[ch], sh = g_shift[ch];
    float4 v = ((const float4*)g_y)[i4];
    v.x = v.x * a + sh;  v.x = v.x * normcdff(v.x);
    v.y = v.y * a + sh;  v.y = v.y * normcdff(v.y);
    v.z = v.z * a + sh;  v.z = v.z * normcdff(v.z);
    v.w = v.w * a + sh;  v.w = v.w * normcdff(v.w);
    ((float4*)out)[i4] = v;
}

// ---------------------------------------------------------------------------
extern "C" void kernel_launch(void* const* d_in, const int* in_sizes, int n_in,
                              void* d_out, int out_size)
{
    const float* x     = (const float*)d_in[0];
    const float* w     = (const float*)d_in[1];
    const float* cbias = (const float*)d_in[2];
    const float* gamma = (const float*)d_in[3];
    const float* beta  = (const float*)d_in[4];
    float* out = (float*)d_out;

    cudaFuncSetAttribute(attn_kernel, cudaFuncAttributeMaxDynamicSharedMemorySize, ATT_SMEM);
    cudaFuncSetAttribute(conv_kernel, cudaFuncAttributeMaxDynamicSharedMemorySize, CV_SMEM);

    prep_kernel<<<dim3((NN + 255) / 256, BB), 256>>>(x);
    wprep_kernel<<<(COUT * 2 * CC + 255) / 256, 256>>>(w);
    attn_kernel<<<dim3(NTILE, BB, KSPLIT), 128, ATT_SMEM>>>();
    attn_fin_kernel<<<(BB * CC * NN / 4 + 255) / 256, 256>>>(x);
    conv_kernel<<<dim3(NTILE, BB), 256, CV_SMEM>>>(cbias);
    bn_fin_kernel<<<1, COUT>>>(gamma, beta);
    bn_gelu_kernel<<<(BB * COUT * NN / 4 + 255) / 256, 256>>>(out);
}

// round 11
// speedup vs baseline: 4.8903x; 1.1368x over previous
#include <cuda_runtime.h>
#include <cuda_fp16.h>
#include <math.h>
#include <stdint.h>

// ---------------- problem constants ----------------
#define BB     8
#define CC     96
#define NN     3136
#define COUT   192
#define TK     64
#define NTILE  49          // NN / TK
#define QTM    64          // query rows per attn block
#define KSPLIT 3

// ---------------- scratch ----------------
__device__ alignas(16) __half g_xhi[BB * CC * NN];
__device__ alignas(16) __half g_xlo[BB * CC * NN];
__device__ alignas(16) __half g_xjhi[BB * CC * NN];
__device__ alignas(16) __half g_xjlo[BB * CC * NN];
__device__ alignas(16) __half g_whi[COUT * 2 * CC];   // transposed [ch][out]
__device__ alignas(16) __half g_wlo[COUT * 2 * CC];
__device__ float g_norm[BB * NN];
__device__ int   g_maxn[BB];
__device__ alignas(16) float g_att[BB * CC * NN];   // O accumulator (atomic)
__device__ alignas(16) float g_l[BB * NN];          // l accumulator (atomic)
__device__ float g_y[BB * COUT * NN];
__device__ float g_sum[COUT];
__device__ float g_sumsq[COUT];
__device__ float g_scale[COUT];
__device__ float g_shift[COUT];

// ---------------- attn smem layout ----------------
#define OFF_QHI 0
#define OFF_QLO 12288
#define OFF_K   24576
#define KSTAGE  24576                   // hi 12288 + lo 12288
#define ATT_SMEM (OFF_K + 2 * KSTAGE)   // 73728

// ---------------- conv smem layout ----------------
#define CV_CAT_HI 0
#define CV_CAT_LO 24576
#define CV_W      49152                 // + stage*12800 ; hi +0, lo +6400
#define CV_SMEM   (CV_W + 2 * 12800)    // 74752 (ysm 49920 reuses front)

// ---------------- PTX helpers ----------------
__device__ __forceinline__ uint32_t smem_u32(const void* p) {
    uint32_t a;
    asm("{ .reg .u64 t; cvta.to.shared.u64 t, %1; cvt.u32.u64 %0, t; }" : "=r"(a) : "l"(p));
    return a;
}
__device__ __forceinline__ uint32_t swk(uint32_t o) { return o ^ ((o >> 3) & 0x70); }

__device__ __forceinline__ void ldsm4(uint32_t* r, uint32_t a) {
    asm volatile("ldmatrix.sync.aligned.m8n8.x4.shared.b16 {%0,%1,%2,%3}, [%4];"
                 : "=r"(r[0]), "=r"(r[1]), "=r"(r[2]), "=r"(r[3]) : "r"(a));
}
__device__ __forceinline__ void ldsm4t(uint32_t* r, uint32_t a) {
    asm volatile("ldmatrix.sync.aligned.m8n8.x4.trans.shared.b16 {%0,%1,%2,%3}, [%4];"
                 : "=r"(r[0]), "=r"(r[1]), "=r"(r[2]), "=r"(r[3]) : "r"(a));
}
__device__ __forceinline__ void mma16816(float* d, const uint32_t* a,
                                         uint32_t b0, uint32_t b1) {
    asm volatile(
        "mma.sync.aligned.m16n8k16.row.col.f32.f16.f16.f32 "
        "{%0,%1,%2,%3}, {%4,%5,%6,%7}, {%8,%9}, {%0,%1,%2,%3};"
        : "+f"(d[0]), "+f"(d[1]), "+f"(d[2]), "+f"(d[3])
        : "r"(a[0]), "r"(a[1]), "r"(a[2]), "r"(a[3]), "r"(b0), "r"(b1));
}
__device__ __forceinline__ void cpasync16(uint32_t dst, const void* src) {
    asm volatile("cp.async.cg.shared.global [%0], [%1], 16;" :: "r"(dst), "l"(src));
}
#define CP_COMMIT() asm volatile("cp.async.commit_group;" ::: "memory")
#define CP_WAIT1()  asm volatile("cp.async.wait_group 1;" ::: "memory")
#define CP_WAIT0()  asm volatile("cp.async.wait_group 0;" ::: "memory")

// pack two floats into fp16x2 (elem0 low half)
__device__ __forceinline__ uint32_t packh2(float a, float b) {
    __half2 h = __floats2half2_rn(a, b);
    return *reinterpret_cast<uint32_t*>(&h);
}
// split two fp32 into fp16 hi + fp16 lo-residual pairs
__device__ __forceinline__ void split2h(float a, float b, uint32_t& hi, uint32_t& lo) {
    __half2 h = __floats2half2_rn(a, b);
    float2 hf = __half22float2(h);
    __half2 l = __floats2half2_rn(a - hf.x, b - hf.y);
    hi = *reinterpret_cast<uint32_t*>(&h);
    lo = *reinterpret_cast<uint32_t*>(&l);
}

// ---------------------------------------------------------------------------
// Kernel 0a: split x -> fp16 hi/lo, token norms, batch max norm, zero O/l accs
// ---------------------------------------------------------------------------
__global__ __launch_bounds__(256)
void prep_kernel(const float* __restrict__ x)
{
    const int b = blockIdx.y;
    const int n = blockIdx.x * 256 + threadIdx.x;
    if (n >= NN) return;
    const float* xb = x + (size_t)b * CC * NN;
    __half* hb = g_xhi + (size_t)b * CC * NN;
    __half* lb = g_xlo + (size_t)b * CC * NN;
    float* ob = g_att + (size_t)b * CC * NN;
    float s = 0.f;
    for (int c = 0; c < CC; c++) {
        float v = xb[c * NN + n];
        __half h = __float2half_rn(v);
        hb[c * NN + n] = h;
        lb[c * NN + n] = __float2half_rn(v - __half2float(h));
        ob[c * NN + n] = 0.f;
        s = fmaf(v, v, s);
    }
    float norm = sqrtf(s);
    g_norm[b * NN + n] = norm;
    g_l[b * NN + n] = 0.f;
    atomicMax(&g_maxn[b], __float_as_int(norm));
}

// ---------------------------------------------------------------------------
// Kernel 0b: split + transpose W, zero BN stat accumulators
// ---------------------------------------------------------------------------
__global__ __launch_bounds__(256)
void wprep_kernel(const float* __restrict__ w)
{
    const int i = blockIdx.x * 256 + threadIdx.x;
    if (i < COUT) { g_sum[i] = 0.f; g_sumsq[i] = 0.f; }
    if (i >= COUT * 2 * CC) return;
    const int o = i / (2 * CC), c = i % (2 * CC);
    float v = w[i];
    __half h = __float2half_rn(v);
    g_whi[c * COUT + o] = h;
    g_wlo[c * COUT + o] = __float2half_rn(v - __half2float(h));
}

// ---------------------------------------------------------------------------
// Kernel 1: warp-MMA fp16-split flash attention, online per-block softmax,
// split-K fp32 atomics in the static-bound reference frame.
// S: 3 products (Qh*Kh + Qh*Kl + Ql*Kh); PV: 1 product (Ph*Vh — V lo dropped:
// P sums to 1, so output err ~5e-4 elementwise max, final ~1e-4 << 1e-3).
// Grid (49, 8, 3) x 128 threads (4 warps; warp w -> query rows 16w..16w+15).
// ---------------------------------------------------------------------------
__global__ __launch_bounds__(128)
void attn_kernel()
{
    extern __shared__ char smc[];
    const uint32_t sb = smem_u32(smc);
    const int tid = threadIdx.x;
    const int lane = tid & 31, warp = tid >> 5;
    const int b  = blockIdx.y;
    const int n0 = blockIdx.x * QTM;
    const int tb = blockIdx.z * 16;
    const int te = (blockIdx.z == KSPLIT - 1) ? NTILE : tb + 16;
    const __half* xh = g_xhi + (size_t)b * CC * NN;
    const __half* xl = g_xlo + (size_t)b * CC * NN;

    // issue Q tile + first K tile (one cp.async group)
    for (int i = tid; i < CC * 8; i += 128) {
        int c = i >> 3, ck = i & 7;
        uint32_t d = swk((uint32_t)(c * 128 + ck * 16));
        cpasync16(sb + OFF_QHI + d, xh + c * NN + n0 + ck * 8);
        cpasync16(sb + OFF_QLO + d, xl + c * NN + n0 + ck * 8);
    }
    {
        const int k0 = tb * TK;
        for (int i = tid; i < CC * 8; i += 128) {
            int c = i >> 3, ck = i & 7;
            uint32_t d = swk((uint32_t)(c * 128 + ck * 16));
            cpasync16(sb + OFF_K + d,         xh + c * NN + k0 + ck * 8);
            cpasync16(sb + OFF_K + 12288 + d, xl + c * NN + k0 + ck * 8);
        }
    }
    CP_COMMIT();

    const float mnorm = __int_as_float(g_maxn[b]);
    const int q0g = warp * 16 + (lane >> 2);
    const int q1g = q0g + 8;
    const float mi0 = g_norm[b * NN + n0 + q0g] * mnorm;  // static upper bound
    const float mi1 = g_norm[b * NN + n0 + q1g] * mnorm;

    float oacc[12][4];
#pragma unroll
    for (int f = 0; f < 12; f++)
#pragma unroll
        for (int e = 0; e < 4; e++) oacc[f][e] = 0.f;
    float l0 = 0.f, l1 = 0.f;
    float m0 = -1e30f, m1 = -1e30f;   // running per-block row max

    uint32_t qah[6][4], qal[6][4];
    const int g  = lane >> 3;
    const int lr = lane & 7;

#pragma unroll 1
    for (int t = tb; t < te; t++) {
        __syncthreads();
        if (t + 1 < te) {
            const int k0 = (t + 1) * TK;
            const uint32_t bs = sb + OFF_K + (uint32_t)((t + 1 - tb) & 1) * KSTAGE;
            for (int i = tid; i < CC * 8; i += 128) {
                int c = i >> 3, ck = i & 7;
                uint32_t d = swk((uint32_t)(c * 128 + ck * 16));
                cpasync16(bs + d,         xh + c * NN + k0 + ck * 8);
                cpasync16(bs + 12288 + d, xl + c * NN + k0 + ck * 8);
            }
            CP_COMMIT();
            CP_WAIT1();
        } else {
            CP_WAIT0();
        }
        __syncthreads();

        if (t == tb) {  // Q fragments (stable afterwards)
#pragma unroll
            for (int k = 0; k < 6; k++) {
                int ch = 16 * k + ((g >= 2) ? 8 : 0) + lr;
                int q  = warp * 16 + ((g & 1) ? 8 : 0);
                uint32_t d = swk((uint32_t)(ch * 128 + q * 2));
                ldsm4t(qah[k], sb + OFF_QHI + d);
                ldsm4t(qal[k], sb + OFF_QLO + d);
            }
        }

        const uint32_t kb = sb + OFF_K + (uint32_t)((t - tb) & 1) * KSTAGE;

        // ---- S = Q K^T (3 split products) ----
        float sacc[8][4];
#pragma unroll
        for (int f = 0; f < 8; f++)
#pragma unroll
            for (int e = 0; e < 4; e++) sacc[f][e] = 0.f;

#pragma unroll
        for (int k = 0; k < 6; k++) {
#pragma unroll
            for (int jp = 0; jp < 4; jp++) {
                int ch  = 16 * k + (g & 1) * 8 + lr;
                int key = 16 * jp + (g >> 1) * 8;
                uint32_t d = swk((uint32_t)(ch * 128 + key * 2));
                uint32_t bh[4], bl[4];
                ldsm4t(bh, kb + d);
                ldsm4t(bl, kb + 12288 + d);
                mma16816(sacc[2 * jp],     qah[k], bh[0], bh[1]);
                mma16816(sacc[2 * jp],     qah[k], bl[0], bl[1]);
                mma16816(sacc[2 * jp],     qal[k], bh[0], bh[1]);
                mma16816(sacc[2 * jp + 1], qah[k], bh[2], bh[3]);
                mma16816(sacc[2 * jp + 1], qah[k], bl[2], bl[3]);
                mma16816(sacc[2 * jp + 1], qal[k], bh[2], bh[3]);
            }
        }

        // ---- online row max; rescale only when the max actually rises ----
        float mx0 = -1e30f, mx1 = -1e30f;
#pragma unroll
        for (int f = 0; f < 8; f++) {
            mx0 = fmaxf(mx0, fmaxf(sacc[f][0], sacc[f][1]));
            mx1 = fmaxf(mx1, fmaxf(sacc[f][2], sacc[f][3]));
        }
        mx0 = fmaxf(mx0, __shfl_xor_sync(0xffffffffu, mx0, 1));
        mx0 = fmaxf(mx0, __shfl_xor_sync(0xffffffffu, mx0, 2));
        mx1 = fmaxf(mx1, __shfl_xor_sync(0xffffffffu, mx1, 1));
        mx1 = fmaxf(mx1, __shfl_xor_sync(0xffffffffu, mx1, 2));
        if (mx0 > m0) {
            float sc0 = __expf(m0 - mx0);   // first tile: exp(-huge) = 0
            m0 = mx0; l0 *= sc0;
#pragma unroll
            for (int f = 0; f < 12; f++) { oacc[f][0] *= sc0; oacc[f][1] *= sc0; }
        }
        if (mx1 > m1) {
            float sc1 = __expf(m1 - mx1);
            m1 = mx1; l1 *= sc1;
#pragma unroll
            for (int f = 0; f < 12; f++) { oacc[f][2] *= sc1; oacc[f][3] *= sc1; }
        }

        // ---- softmax (thread-local, p near 1) -> single fp16 P A-frags ----
        uint32_t pah[4][4];
#pragma unroll
        for (int jj = 0; jj < 4; jj++) {
            float p0 = __expf(sacc[2 * jj][0] - m0);
            float p1 = __expf(sacc[2 * jj][1] - m0);
            float p2 = __expf(sacc[2 * jj][2] - m1);
            float p3 = __expf(sacc[2 * jj][3] - m1);
            float p4 = __expf(sacc[2 * jj + 1][0] - m0);
            float p5 = __expf(sacc[2 * jj + 1][1] - m0);
            float p6 = __expf(sacc[2 * jj + 1][2] - m1);
            float p7 = __expf(sacc[2 * jj + 1][3] - m1);
            l0 += (p0 + p1) + (p4 + p5);
            l1 += (p2 + p3) + (p6 + p7);
            pah[jj][0] = packh2(p0, p1);
            pah[jj][1] = packh2(p2, p3);
            pah[jj][2] = packh2(p4, p5);
            pah[jj][3] = packh2(p6, p7);
        }

        // ---- O += P V (single product: Ph*Vh) ----
#pragma unroll
        for (int jj = 0; jj < 4; jj++) {
#pragma unroll
            for (int cp = 0; cp < 6; cp++) {
                int ch  = 8 * (2 * cp + (g >> 1)) + lr;
                int key = 16 * jj + (g & 1) * 8;
                uint32_t d = swk((uint32_t)(ch * 128 + key * 2));
                uint32_t bh[4];
                ldsm4(bh, kb + d);
                mma16816(oacc[2 * cp],     pah[jj], bh[0], bh[1]);
                mma16816(oacc[2 * cp + 1], pah[jj], bh[2], bh[3]);
            }
        }
    }

    // ---- epilogue: rescale to global (static-bound) frame in fp32, atomics --
    const float f0 = __expf(m0 - mi0);   // <= 1, fp32 range
    const float f1 = __expf(m1 - mi1);

    l0 += __shfl_xor_sync(0xffffffffu, l0, 1);
    l0 += __shfl_xor_sync(0xffffffffu, l0, 2);
    l1 += __shfl_xor_sync(0xffffffffu, l1, 1);
    l1 += __shfl_xor_sync(0xffffffffu, l1, 2);

    float* ob = g_att + (size_t)b * CC * NN + n0;
#pragma unroll
    for (int nf = 0; nf < 12; nf++) {
        int c = 8 * nf + 2 * (lane & 3);
        atomicAdd(&ob[c * NN + q0g],       oacc[nf][0] * f0);
        atomicAdd(&ob[(c + 1) * NN + q0g], oacc[nf][1] * f0);
        atomicAdd(&ob[c * NN + q1g],       oacc[nf][2] * f1);
        atomicAdd(&ob[(c + 1) * NN + q1g], oacc[nf][3] * f1);
    }
    if ((lane & 3) == 0) {
        atomicAdd(&g_l[b * NN + n0 + q0g], l0 * f0);
        atomicAdd(&g_l[b * NN + n0 + q1g], l1 * f1);
    }
}

// ---------------------------------------------------------------------------
// Kernel 2: finalize attention: xj = relu(x - O/l) -> fp16 hi/lo
// ---------------------------------------------------------------------------
__global__ __launch_bounds__(256)
void attn_fin_kernel(const float* __restrict__ x)
{
    const int i4 = blockIdx.x * 256 + threadIdx.x;
    const int per = CC * NN / 4;
    if (i4 >= BB * per) return;
    const int b = i4 / per, r = i4 - b * per;
    const int n4 = r % (NN / 4);
    float4 o  = ((const float4*)g_att)[i4];
    float4 lv = ((const float4*)g_l)[b * (NN / 4) + n4];
    float4 xv = ((const float4*)x)[i4];
    float j0 = fmaxf(xv.x - o.x / lv.x, 0.f);
    float j1 = fmaxf(xv.y - o.y / lv.y, 0.f);
    float j2 = fmaxf(xv.z - o.z / lv.z, 0.f);
    float j3 = fmaxf(xv.w - o.w / lv.w, 0.f);
    uint2 hi, lo;
    split2h(j0, j1, hi.x, lo.x);
    split2h(j2, j3, hi.y, lo.y);
    ((uint2*)g_xjhi)[i4] = hi;
    ((uint2*)g_xjlo)[i4] = lo;
}

// ---------------------------------------------------------------------------
// Kernel 3: 1x1 conv via fp16-split MMA (3 products) + bias + fused BN stats
// Grid (49, 8) x 256 threads (8 warps: wy=warp>>1 -> 48 out rows, wx -> 32 tok)
// ---------------------------------------------------------------------------
__global__ __launch_bounds__(256)
void conv_kernel(const float* __restrict__ bias)
{
    extern __shared__ char smc[];
    const uint32_t sb = smem_u32(smc);
    const int tid = threadIdx.x;
    const int lane = tid & 31, warp = tid >> 5;
    const int wy = warp >> 1, wx = warp & 1;
    const int b = blockIdx.y, n0 = blockIdx.x * 64;
    const __half* xh = g_xhi  + (size_t)b * CC * NN;
    const __half* xl = g_xlo  + (size_t)b * CC * NN;
    const __half* jh = g_xjhi + (size_t)b * CC * NN;
    const __half* jl = g_xjlo + (size_t)b * CC * NN;

    // cat tile [192 ch][64 tok] + W chunk 0 (one group)
    for (int i = tid; i < 192 * 8; i += 256) {
        int c = i >> 3, ck = i & 7;
        uint32_t d = swk((uint32_t)(c * 128 + ck * 16));
        const __half* sh = (c < CC) ? (xh + c * NN) : (jh + (c - CC) * NN);
        const __half* sl = (c < CC) ? (xl + c * NN) : (jl + (c - CC) * NN);
        cpasync16(sb + CV_CAT_HI + d, sh + n0 + ck * 8);
        cpasync16(sb + CV_CAT_LO + d, sl + n0 + ck * 8);
    }
    for (int i = tid; i < 16 * 24; i += 256) {
        int rr = i / 24, cc = i % 24;
        cpasync16(sb + CV_W + rr * 400 + cc * 16,        g_whi + rr * COUT + cc * 8);
        cpasync16(sb + CV_W + 6400 + rr * 400 + cc * 16, g_wlo + rr * COUT + cc * 8);
    }
    CP_COMMIT();

    float cacc[3][4][4];
#pragma unroll
    for (int m = 0; m < 3; m++)
#pragma unroll
        for (int n = 0; n < 4; n++)
#pragma unroll
            for (int e = 0; e < 4; e++) cacc[m][n][e] = 0.f;

    const int g = lane >> 3, lr = lane & 7;

#pragma unroll 1
    for (int k = 0; k < 12; k++) {
        if (k + 1 < 12) {
            const uint32_t wb = sb + CV_W + (uint32_t)((k + 1) & 1) * 12800;
            const int k0n = (k + 1) * 16;
            for (int i = tid; i < 16 * 24; i += 256) {
                int rr = i / 24, cc = i % 24;
                cpasync16(wb + rr * 400 + cc * 16,        g_whi + (k0n + rr) * COUT + cc * 8);
                cpasync16(wb + 6400 + rr * 400 + cc * 16, g_wlo + (k0n + rr) * COUT + cc * 8);
            }
            CP_COMMIT();
            CP_WAIT1();
        } else {
            CP_WAIT0();
        }
        __syncthreads();

        const uint32_t wb = sb + CV_W + (uint32_t)(k & 1) * 12800;
        uint32_t ah[3][4], al[3][4];
#pragma unroll
        for (int mf = 0; mf < 3; mf++) {
            int out = 48 * wy + 16 * mf + ((g & 1) ? 8 : 0);
            int chh = ((g >= 2) ? 8 : 0) + lr;
            uint32_t d = (uint32_t)(chh * 400 + out * 2);
            ldsm4t(ah[mf], wb + d);
            ldsm4t(al[mf], wb + 6400 + d);
        }
#pragma unroll
        for (int jp = 0; jp < 2; jp++) {
            int ch  = k * 16 + (g & 1) * 8 + lr;
            int key = 32 * wx + 16 * jp + (g >> 1) * 8;
            uint32_t d = swk((uint32_t)(ch * 128 + key * 2));
            uint32_t bh[4], bl[4];
            ldsm4t(bh, sb + CV_CAT_HI + d);
            ldsm4t(bl, sb + CV_CAT_LO + d);
#pragma unroll
            for (int mf = 0; mf < 3; mf++) {
                mma16816(cacc[mf][2 * jp],     ah[mf], bh[0], bh[1]);
                mma16816(cacc[mf][2 * jp],     ah[mf], bl[0], bl[1]);
                mma16816(cacc[mf][2 * jp],     al[mf], bh[0], bh[1]);
                mma16816(cacc[mf][2 * jp + 1], ah[mf], bh[2], bh[3]);
                mma16816(cacc[mf][2 * jp + 1], ah[mf], bl[2], bl[3]);
                mma16816(cacc[mf][2 * jp + 1], al[mf], bh[2], bh[3]);
            }
        }
        __syncthreads();
    }

    // ---- bias, stage y in smem (stride 65 floats) ----
    float* ys = (float*)smc;
#pragma unroll
    for (int mf = 0; mf < 3; mf++) {
        int r0 = 48 * wy + 16 * mf + (lane >> 2);
        float b0 = bias[r0], b1 = bias[r0 + 8];
#pragma unroll
        for (int nf = 0; nf < 4; nf++) {
            int tok = 32 * wx + 8 * nf + 2 * (lane & 3);
            ys[r0 * 65 + tok]           = cacc[mf][nf][0] + b0;
            ys[r0 * 65 + tok + 1]       = cacc[mf][nf][1] + b0;
            ys[(r0 + 8) * 65 + tok]     = cacc[mf][nf][2] + b1;
            ys[(r0 + 8) * 65 + tok + 1] = cacc[mf][nf][3] + b1;
        }
    }
    __syncthreads();

    // ---- partial BN stats ----
    if (tid < COUT) {
        float s = 0.f, ss = 0.f;
#pragma unroll 4
        for (int i = 0; i < 64; i++) {
            float v = ys[tid * 65 + i];
            s += v; ss = fmaf(v, v, ss);
        }
        atomicAdd(&g_sum[tid], s);
        atomicAdd(&g_sumsq[tid], ss);
    }

    // ---- write y (coalesced) ----
    float* yb = g_y + (size_t)b * COUT * NN + n0;
    for (int i = tid; i < COUT * 64; i += 256) {
        int rr = i >> 6, cc = i & 63;
        yb[rr * NN + cc] = ys[rr * 65 + cc];
    }
}

// ---------------------------------------------------------------------------
// Kernel 4: BN scale/shift from accumulated stats
// ---------------------------------------------------------------------------
__global__ void bn_fin_kernel(const float* __restrict__ gamma,
                              const float* __restrict__ beta)
{
    const int c = threadIdx.x;
    if (c >= COUT) return;
    const float cnt = (float)(BB * NN);
    float mean = g_sum[c] / cnt;
    float var  = g_sumsq[c] / cnt - mean * mean;
    float a    = gamma[c] * rsqrtf(var + 1e-5f);
    g_scale[c] = a;
    g_shift[c] = beta[c] - mean * a;
}

// ---------------------------------------------------------------------------
// Kernel 5: BN apply + exact GELU
// ---------------------------------------------------------------------------
__global__ __launch_bounds__(256)
void bn_gelu_kernel(float* __restrict__ out)
{
    const int i4 = blockIdx.x * blockDim.x + threadIdx.x;
    const int total4 = BB * COUT * NN / 4;
    if (i4 >= total4) return;
    const int ch = (i4 / (NN / 4)) % COUT;
    const float a = g_scale[ch], sh = g_shift[ch];
    float4 v = ((const float4*)g_y)[i4];
    v.x = v.x * a + sh;  v.x = v.x * normcdff(v.x);
    v.y = v.y * a + sh;  v.y = v.y * normcdff(v.y);
    v.z = v.z * a + sh;  v.z = v.z * normcdff(v.z);
    v.w = v.w * a + sh;  v.w = v.w * normcdff(v.w);
    ((float4*)out)[i4] = v;
}

// ---------------------------------------------------------------------------
extern "C" void kernel_launch(void* const* d_in, const int* in_sizes, int n_in,
                              void* d_out, int out_size)
{
    const float* x     = (const float*)d_in[0];
    const float* w     = (const float*)d_in[1];
    const float* cbias = (const float*)d_in[2];
    const float* gamma = (const float*)d_in[3];
    const float* beta  = (const float*)d_in[4];
    float* out = (float*)d_out;

    cudaFuncSetAttribute(attn_kernel, cudaFuncAttributeMaxDynamicSharedMemorySize, ATT_SMEM);
    cudaFuncSetAttribute(conv_kernel, cudaFuncAttributeMaxDynamicSharedMemorySize, CV_SMEM);

    prep_kernel<<<dim3((NN + 255) / 256, BB), 256>>>(x);
    wprep_kernel<<<(COUT * 2 * CC + 255) / 256, 256>>>(w);
    attn_kernel<<<dim3(NTILE, BB, KSPLIT), 128, ATT_SMEM>>>();
    attn_fin_kernel<<<(BB * CC * NN / 4 + 255) / 256, 256>>>(x);
    conv_kernel<<<dim3(NTILE, BB), 256, CV_SMEM>>>(cbias);
    bn_fin_kernel<<<1, COUT>>>(gamma, beta);
    bn_gelu_kernel<<<(BB * COUT * NN / 4 + 255) / 256, 256>>>(out);
}

// round 12
// speedup vs baseline: 4.9935x; 1.0211x over previous
#include <cuda_runtime.h>
#include <cuda_fp16.h>
#include <math.h>
#include <stdint.h>

// ---------------- problem constants ----------------
#define BB     8
#define CC     96
#define NN     3136
#define COUT   192
#define TK     64
#define NTILE  49          // NN / TK
#define QTM    64          // query rows per attn block
#define KSPLIT 3

// ---------------- scratch ----------------
__device__ alignas(16) __half g_xhi[BB * CC * NN];
__device__ alignas(16) __half g_xlo[BB * CC * NN];
__device__ alignas(16) __half g_xjhi[BB * CC * NN];
__device__ alignas(16) __half g_xjlo[BB * CC * NN];
__device__ alignas(16) __half g_whi[COUT * 2 * CC];   // transposed [ch][out]
__device__ alignas(16) __half g_wlo[COUT * 2 * CC];
__device__ float g_norm[BB * NN];
__device__ int   g_maxn[BB];
__device__ alignas(16) float g_att[BB * CC * NN];   // O accumulator (atomic)
__device__ alignas(16) float g_l[BB * NN];          // l accumulator (atomic)
__device__ float g_y[BB * COUT * NN];
__device__ float g_sum[COUT];
__device__ float g_sumsq[COUT];

// ---------------- attn smem layout ----------------
#define OFF_QHI 0
#define OFF_QLO 12288
#define OFF_K   24576
#define KSTAGE  24576                   // hi 12288 + lo 12288
#define ATT_SMEM (OFF_K + 2 * KSTAGE)   // 73728

// ---------------- conv smem layout (z-split: 96 outputs/block) ----------------
#define CV_CAT_HI 0
#define CV_CAT_LO 24576
#define CV_W      49152                 // + stage*6656 ; hi +0, lo +3328
#define CV_WHALF  3328                  // 16 rows x 208B
#define CV_WSTAGE 6656
#define CV_SMEM   (CV_W + 2 * CV_WSTAGE)  // 62464 (ysm 24960 reuses front)

// ---------------- PTX helpers ----------------
__device__ __forceinline__ uint32_t smem_u32(const void* p) {
    uint32_t a;
    asm("{ .reg .u64 t; cvta.to.shared.u64 t, %1; cvt.u32.u64 %0, t; }" : "=r"(a) : "l"(p));
    return a;
}
__device__ __forceinline__ uint32_t swk(uint32_t o) { return o ^ ((o >> 3) & 0x70); }

__device__ __forceinline__ void ldsm4(uint32_t* r, uint32_t a) {
    asm volatile("ldmatrix.sync.aligned.m8n8.x4.shared.b16 {%0,%1,%2,%3}, [%4];"
                 : "=r"(r[0]), "=r"(r[1]), "=r"(r[2]), "=r"(r[3]) : "r"(a));
}
__device__ __forceinline__ void ldsm4t(uint32_t* r, uint32_t a) {
    asm volatile("ldmatrix.sync.aligned.m8n8.x4.trans.shared.b16 {%0,%1,%2,%3}, [%4];"
                 : "=r"(r[0]), "=r"(r[1]), "=r"(r[2]), "=r"(r[3]) : "r"(a));
}
__device__ __forceinline__ void mma16816(float* d, const uint32_t* a,
                                         uint32_t b0, uint32_t b1) {
    asm volatile(
        "mma.sync.aligned.m16n8k16.row.col.f32.f16.f16.f32 "
        "{%0,%1,%2,%3}, {%4,%5,%6,%7}, {%8,%9}, {%0,%1,%2,%3};"
        : "+f"(d[0]), "+f"(d[1]), "+f"(d[2]), "+f"(d[3])
        : "r"(a[0]), "r"(a[1]), "r"(a[2]), "r"(a[3]), "r"(b0), "r"(b1));
}
__device__ __forceinline__ void cpasync16(uint32_t dst, const void* src) {
    asm volatile("cp.async.cg.shared.global [%0], [%1], 16;" :: "r"(dst), "l"(src));
}
#define CP_COMMIT() asm volatile("cp.async.commit_group;" ::: "memory")
#define CP_WAIT1()  asm volatile("cp.async.wait_group 1;" ::: "memory")
#define CP_WAIT0()  asm volatile("cp.async.wait_group 0;" ::: "memory")

// pack two floats into fp16x2 (elem0 low half)
__device__ __forceinline__ uint32_t packh2(float a, float b) {
    __half2 h = __floats2half2_rn(a, b);
    return *reinterpret_cast<uint32_t*>(&h);
}
// split two fp32 into fp16 hi + fp16 lo-residual pairs
__device__ __forceinline__ void split2h(float a, float b, uint32_t& hi, uint32_t& lo) {
    __half2 h = __floats2half2_rn(a, b);
    float2 hf = __half22float2(h);
    __half2 l = __floats2half2_rn(a - hf.x, b - hf.y);
    hi = *reinterpret_cast<uint32_t*>(&h);
    lo = *reinterpret_cast<uint32_t*>(&l);
}

// ---------------------------------------------------------------------------
// Kernel 0a: split x -> fp16 hi/lo, token norms, batch max norm, zero O/l accs
// ---------------------------------------------------------------------------
__global__ __launch_bounds__(256)
void prep_kernel(const float* __restrict__ x)
{
    const int b = blockIdx.y;
    const int n = blockIdx.x * 256 + threadIdx.x;
    if (n >= NN) return;
    const float* xb = x + (size_t)b * CC * NN;
    __half* hb = g_xhi + (size_t)b * CC * NN;
    __half* lb = g_xlo + (size_t)b * CC * NN;
    float* ob = g_att + (size_t)b * CC * NN;
    float s = 0.f;
    for (int c = 0; c < CC; c++) {
        float v = xb[c * NN + n];
        __half h = __float2half_rn(v);
        hb[c * NN + n] = h;
        lb[c * NN + n] = __float2half_rn(v - __half2float(h));
        ob[c * NN + n] = 0.f;
        s = fmaf(v, v, s);
    }
    float norm = sqrtf(s);
    g_norm[b * NN + n] = norm;
    g_l[b * NN + n] = 0.f;
    atomicMax(&g_maxn[b], __float_as_int(norm));
}

// ---------------------------------------------------------------------------
// Kernel 0b: split + transpose W, zero BN stat accumulators
// ---------------------------------------------------------------------------
__global__ __launch_bounds__(256)
void wprep_kernel(const float* __restrict__ w)
{
    const int i = blockIdx.x * 256 + threadIdx.x;
    if (i < COUT) { g_sum[i] = 0.f; g_sumsq[i] = 0.f; }
    if (i >= COUT * 2 * CC) return;
    const int o = i / (2 * CC), c = i % (2 * CC);
    float v = w[i];
    __half h = __float2half_rn(v);
    g_whi[c * COUT + o] = h;
    g_wlo[c * COUT + o] = __float2half_rn(v - __half2float(h));
}

// ---------------------------------------------------------------------------
// Kernel 1: warp-MMA fp16-split flash attention, online per-block softmax,
// split-K fp32 atomics in the static-bound reference frame.
// S: 3 products; PV: 1 product (Ph*Vh).
// Grid (49, 8, 3) x 128 threads; target 3 blocks/SM (regs capped at 166).
// ---------------------------------------------------------------------------
__global__ __launch_bounds__(128, 3)
void attn_kernel()
{
    extern __shared__ char smc[];
    const uint32_t sb = smem_u32(smc);
    const int tid = threadIdx.x;
    const int lane = tid & 31, warp = tid >> 5;
    const int b  = blockIdx.y;
    const int n0 = blockIdx.x * QTM;
    const int tb = blockIdx.z * 16;
    const int te = (blockIdx.z == KSPLIT - 1) ? NTILE : tb + 16;
    const __half* xh = g_xhi + (size_t)b * CC * NN;
    const __half* xl = g_xlo + (size_t)b * CC * NN;

    // issue Q tile + first K tile (one cp.async group)
    for (int i = tid; i < CC * 8; i += 128) {
        int c = i >> 3, ck = i & 7;
        uint32_t d = swk((uint32_t)(c * 128 + ck * 16));
        cpasync16(sb + OFF_QHI + d, xh + c * NN + n0 + ck * 8);
        cpasync16(sb + OFF_QLO + d, xl + c * NN + n0 + ck * 8);
    }
    {
        const int k0 = tb * TK;
        for (int i = tid; i < CC * 8; i += 128) {
            int c = i >> 3, ck = i & 7;
            uint32_t d = swk((uint32_t)(c * 128 + ck * 16));
            cpasync16(sb + OFF_K + d,         xh + c * NN + k0 + ck * 8);
            cpasync16(sb + OFF_K + 12288 + d, xl + c * NN + k0 + ck * 8);
        }
    }
    CP_COMMIT();

    const float mnorm = __int_as_float(g_maxn[b]);
    const int q0g = warp * 16 + (lane >> 2);
    const int q1g = q0g + 8;
    const float mi0 = g_norm[b * NN + n0 + q0g] * mnorm;  // static upper bound
    const float mi1 = g_norm[b * NN + n0 + q1g] * mnorm;

    float oacc[12][4];
#pragma unroll
    for (int f = 0; f < 12; f++)
#pragma unroll
        for (int e = 0; e < 4; e++) oacc[f][e] = 0.f;
    float l0 = 0.f, l1 = 0.f;
    float m0 = -1e30f, m1 = -1e30f;   // running per-block row max

    uint32_t qah[6][4], qal[6][4];
    const int g  = lane >> 3;
    const int lr = lane & 7;

#pragma unroll 1
    for (int t = tb; t < te; t++) {
        __syncthreads();
        if (t + 1 < te) {
            const int k0 = (t + 1) * TK;
            const uint32_t bs = sb + OFF_K + (uint32_t)((t + 1 - tb) & 1) * KSTAGE;
            for (int i = tid; i < CC * 8; i += 128) {
                int c = i >> 3, ck = i & 7;
                uint32_t d = swk((uint32_t)(c * 128 + ck * 16));
                cpasync16(bs + d,         xh + c * NN + k0 + ck * 8);
                cpasync16(bs + 12288 + d, xl + c * NN + k0 + ck * 8);
            }
            CP_COMMIT();
            CP_WAIT1();
        } else {
            CP_WAIT0();
        }
        __syncthreads();

        if (t == tb) {  // Q fragments (stable afterwards)
#pragma unroll
            for (int k = 0; k < 6; k++) {
                int ch = 16 * k + ((g >= 2) ? 8 : 0) + lr;
                int q  = warp * 16 + ((g & 1) ? 8 : 0);
                uint32_t d = swk((uint32_t)(ch * 128 + q * 2));
                ldsm4t(qah[k], sb + OFF_QHI + d);
                ldsm4t(qal[k], sb + OFF_QLO + d);
            }
        }

        const uint32_t kb = sb + OFF_K + (uint32_t)((t - tb) & 1) * KSTAGE;

        // ---- S = Q K^T (3 split products) ----
        float sacc[8][4];
#pragma unroll
        for (int f = 0; f < 8; f++)
#pragma unroll
            for (int e = 0; e < 4; e++) sacc[f][e] = 0.f;

#pragma unroll
        for (int k = 0; k < 6; k++) {
#pragma unroll
            for (int jp = 0; jp < 4; jp++) {
                int ch  = 16 * k + (g & 1) * 8 + lr;
                int key = 16 * jp + (g >> 1) * 8;
                uint32_t d = swk((uint32_t)(ch * 128 + key * 2));
                uint32_t bh[4], bl[4];
                ldsm4t(bh, kb + d);
                ldsm4t(bl, kb + 12288 + d);
                mma16816(sacc[2 * jp],     qah[k], bh[0], bh[1]);
                mma16816(sacc[2 * jp],     qah[k], bl[0], bl[1]);
                mma16816(sacc[2 * jp],     qal[k], bh[0], bh[1]);
                mma16816(sacc[2 * jp + 1], qah[k], bh[2], bh[3]);
                mma16816(sacc[2 * jp + 1], qah[k], bl[2], bl[3]);
                mma16816(sacc[2 * jp + 1], qal[k], bh[2], bh[3]);
            }
        }

        // ---- online row max; rescale only when the max actually rises ----
        float mx0 = -1e30f, mx1 = -1e30f;
#pragma unroll
        for (int f = 0; f < 8; f++) {
            mx0 = fmaxf(mx0, fmaxf(sacc[f][0], sacc[f][1]));
            mx1 = fmaxf(mx1, fmaxf(sacc[f][2], sacc[f][3]));
        }
        mx0 = fmaxf(mx0, __shfl_xor_sync(0xffffffffu, mx0, 1));
        mx0 = fmaxf(mx0, __shfl_xor_sync(0xffffffffu, mx0, 2));
        mx1 = fmaxf(mx1, __shfl_xor_sync(0xffffffffu, mx1, 1));
        mx1 = fmaxf(mx1, __shfl_xor_sync(0xffffffffu, mx1, 2));
        if (mx0 > m0) {
            float sc0 = __expf(m0 - mx0);   // first tile: exp(-huge) = 0
            m0 = mx0; l0 *= sc0;
#pragma unroll
            for (int f = 0; f < 12; f++) { oacc[f][0] *= sc0; oacc[f][1] *= sc0; }
        }
        if (mx1 > m1) {
            float sc1 = __expf(m1 - mx1);
            m1 = mx1; l1 *= sc1;
#pragma unroll
            for (int f = 0; f < 12; f++) { oacc[f][2] *= sc1; oacc[f][3] *= sc1; }
        }

        // ---- softmax (thread-local, p near 1) -> single fp16 P A-frags ----
        uint32_t pah[4][4];
#pragma unroll
        for (int jj = 0; jj < 4; jj++) {
            float p0 = __expf(sacc[2 * jj][0] - m0);
            float p1 = __expf(sacc[2 * jj][1] - m0);
            float p2 = __expf(sacc[2 * jj][2] - m1);
            float p3 = __expf(sacc[2 * jj][3] - m1);
            float p4 = __expf(sacc[2 * jj + 1][0] - m0);
            float p5 = __expf(sacc[2 * jj + 1][1] - m0);
            float p6 = __expf(sacc[2 * jj + 1][2] - m1);
            float p7 = __expf(sacc[2 * jj + 1][3] - m1);
            l0 += (p0 + p1) + (p4 + p5);
            l1 += (p2 + p3) + (p6 + p7);
            pah[jj][0] = packh2(p0, p1);
            pah[jj][1] = packh2(p2, p3);
            pah[jj][2] = packh2(p4, p5);
            pah[jj][3] = packh2(p6, p7);
        }

        // ---- O += P V (single product: Ph*Vh) ----
#pragma unroll
        for (int jj = 0; jj < 4; jj++) {
#pragma unroll
            for (int cp = 0; cp < 6; cp++) {
                int ch  = 8 * (2 * cp + (g >> 1)) + lr;
                int key = 16 * jj + (g & 1) * 8;
                uint32_t d = swk((uint32_t)(ch * 128 + key * 2));
                uint32_t bh[4];
                ldsm4(bh, kb + d);
                mma16816(oacc[2 * cp],     pah[jj], bh[0], bh[1]);
                mma16816(oacc[2 * cp + 1], pah[jj], bh[2], bh[3]);
            }
        }
    }

    // ---- epilogue: rescale to global (static-bound) frame in fp32, atomics --
    const float f0 = __expf(m0 - mi0);   // <= 1, fp32 range
    const float f1 = __expf(m1 - mi1);

    l0 += __shfl_xor_sync(0xffffffffu, l0, 1);
    l0 += __shfl_xor_sync(0xffffffffu, l0, 2);
    l1 += __shfl_xor_sync(0xffffffffu, l1, 1);
    l1 += __shfl_xor_sync(0xffffffffu, l1, 2);

    float* ob = g_att + (size_t)b * CC * NN + n0;
#pragma unroll
    for (int nf = 0; nf < 12; nf++) {
        int c = 8 * nf + 2 * (lane & 3);
        atomicAdd(&ob[c * NN + q0g],       oacc[nf][0] * f0);
        atomicAdd(&ob[(c + 1) * NN + q0g], oacc[nf][1] * f0);
        atomicAdd(&ob[c * NN + q1g],       oacc[nf][2] * f1);
        atomicAdd(&ob[(c + 1) * NN + q1g], oacc[nf][3] * f1);
    }
    if ((lane & 3) == 0) {
        atomicAdd(&g_l[b * NN + n0 + q0g], l0 * f0);
        atomicAdd(&g_l[b * NN + n0 + q1g], l1 * f1);
    }
}

// ---------------------------------------------------------------------------
// Kernel 2: finalize attention: xj = relu(x - O/l) -> fp16 hi/lo
// ---------------------------------------------------------------------------
__global__ __launch_bounds__(256)
void attn_fin_kernel(const float* __restrict__ x)
{
    const int i4 = blockIdx.x * 256 + threadIdx.x;
    const int per = CC * NN / 4;
    if (i4 >= BB * per) return;
    const int b = i4 / per, r = i4 - b * per;
    const int n4 = r % (NN / 4);
    float4 o  = ((const float4*)g_att)[i4];
    float4 lv = ((const float4*)g_l)[b * (NN / 4) + n4];
    float4 xv = ((const float4*)x)[i4];
    float j0 = fmaxf(xv.x - o.x / lv.x, 0.f);
    float j1 = fmaxf(xv.y - o.y / lv.y, 0.f);
    float j2 = fmaxf(xv.z - o.z / lv.z, 0.f);
    float j3 = fmaxf(xv.w - o.w / lv.w, 0.f);
    uint2 hi, lo;
    split2h(j0, j1, hi.x, lo.x);
    split2h(j2, j3, hi.y, lo.y);
    ((uint2*)g_xjhi)[i4] = hi;
    ((uint2*)g_xjlo)[i4] = lo;
}

// ---------------------------------------------------------------------------
// Kernel 3: 1x1 conv via fp16-split MMA (3 products) + bias + fused BN stats
// Grid (49, 8, 2) x 128 threads; each block: 96 out channels x 64 tokens.
// Warps: wy=warp>>1 -> 48 out rows, wx=warp&1 -> 32 tokens.
// ---------------------------------------------------------------------------
__global__ __launch_bounds__(128)
void conv_kernel(const float* __restrict__ bias)
{
    extern __shared__ char smc[];
    const uint32_t sb = smem_u32(smc);
    const int tid = threadIdx.x;
    const int lane = tid & 31, warp = tid >> 5;
    const int wy = warp >> 1, wx = warp & 1;
    const int b = blockIdx.y, n0 = blockIdx.x * 64;
    const int zo = blockIdx.z * 96;
    const __half* xh = g_xhi  + (size_t)b * CC * NN;
    const __half* xl = g_xlo  + (size_t)b * CC * NN;
    const __half* jh = g_xjhi + (size_t)b * CC * NN;
    const __half* jl = g_xjlo + (size_t)b * CC * NN;

    // cat tile [192 ch][64 tok] + W chunk 0 (one group)
    for (int i = tid; i < 192 * 8; i += 128) {
        int c = i >> 3, ck = i & 7;
        uint32_t d = swk((uint32_t)(c * 128 + ck * 16));
        const __half* sh = (c < CC) ? (xh + c * NN) : (jh + (c - CC) * NN);
        const __half* sl = (c < CC) ? (xl + c * NN) : (jl + (c - CC) * NN);
        cpasync16(sb + CV_CAT_HI + d, sh + n0 + ck * 8);
        cpasync16(sb + CV_CAT_LO + d, sl + n0 + ck * 8);
    }
    for (int i = tid; i < 16 * 12; i += 128) {
        int rr = i / 12, cc = i % 12;
        cpasync16(sb + CV_W + rr * 208 + cc * 16,            g_whi + rr * COUT + zo + cc * 8);
        cpasync16(sb + CV_W + CV_WHALF + rr * 208 + cc * 16, g_wlo + rr * COUT + zo + cc * 8);
    }
    CP_COMMIT();

    float cacc[3][4][4];
#pragma unroll
    for (int m = 0; m < 3; m++)
#pragma unroll
        for (int n = 0; n < 4; n++)
#pragma unroll
            for (int e = 0; e < 4; e++) cacc[m][n][e] = 0.f;

    const int g = lane >> 3, lr = lane & 7;

#pragma unroll 1
    for (int k = 0; k < 12; k++) {
        if (k + 1 < 12) {
            const uint32_t wb = sb + CV_W + (uint32_t)((k + 1) & 1) * CV_WSTAGE;
            const int k0n = (k + 1) * 16;
            for (int i = tid; i < 16 * 12; i += 128) {
                int rr = i / 12, cc = i % 12;
                cpasync16(wb + rr * 208 + cc * 16,            g_whi + (k0n + rr) * COUT + zo + cc * 8);
                cpasync16(wb + CV_WHALF + rr * 208 + cc * 16, g_wlo + (k0n + rr) * COUT + zo + cc * 8);
            }
            CP_COMMIT();
            CP_WAIT1();
        } else {
            CP_WAIT0();
        }
        __syncthreads();

        const uint32_t wb = sb + CV_W + (uint32_t)(k & 1) * CV_WSTAGE;
        uint32_t ah[3][4], al[3][4];
#pragma unroll
        for (int mf = 0; mf < 3; mf++) {
            int out = 48 * wy + 16 * mf + ((g & 1) ? 8 : 0);
            int chh = ((g >= 2) ? 8 : 0) + lr;
            uint32_t d = (uint32_t)(chh * 208 + out * 2);
            ldsm4t(ah[mf], wb + d);
            ldsm4t(al[mf], wb + CV_WHALF + d);
        }
#pragma unroll
        for (int jp = 0; jp < 2; jp++) {
            int ch  = k * 16 + (g & 1) * 8 + lr;
            int key = 32 * wx + 16 * jp + (g >> 1) * 8;
            uint32_t d = swk((uint32_t)(ch * 128 + key * 2));
            uint32_t bh[4], bl[4];
            ldsm4t(bh, sb + CV_CAT_HI + d);
            ldsm4t(bl, sb + CV_CAT_LO + d);
#pragma unroll
            for (int mf = 0; mf < 3; mf++) {
                mma16816(cacc[mf][2 * jp],     ah[mf], bh[0], bh[1]);
                mma16816(cacc[mf][2 * jp],     ah[mf], bl[0], bl[1]);
                mma16816(cacc[mf][2 * jp],     al[mf], bh[0], bh[1]);
                mma16816(cacc[mf][2 * jp + 1], ah[mf], bh[2], bh[3]);
                mma16816(cacc[mf][2 * jp + 1], ah[mf], bl[2], bl[3]);
                mma16816(cacc[mf][2 * jp + 1], al[mf], bh[2], bh[3]);
            }
        }
        __syncthreads();
    }

    // ---- bias, stage y in smem (96 rows, stride 65 floats) ----
    float* ys = (float*)smc;
#pragma unroll
    for (int mf = 0; mf < 3; mf++) {
        int r0 = 48 * wy + 16 * mf + (lane >> 2);
        float b0 = bias[zo + r0], b1 = bias[zo + r0 + 8];
#pragma unroll
        for (int nf = 0; nf < 4; nf++) {
            int tok = 32 * wx + 8 * nf + 2 * (lane & 3);
            ys[r0 * 65 + tok]           = cacc[mf][nf][0] + b0;
            ys[r0 * 65 + tok + 1]       = cacc[mf][nf][1] + b0;
            ys[(r0 + 8) * 65 + tok]     = cacc[mf][nf][2] + b1;
            ys[(r0 + 8) * 65 + tok + 1] = cacc[mf][nf][3] + b1;
        }
    }
    __syncthreads();

    // ---- partial BN stats (96 channels/block) ----
    if (tid < 96) {
        float s = 0.f, ss = 0.f;
#pragma unroll 4
        for (int i = 0; i < 64; i++) {
            float v = ys[tid * 65 + i];
            s += v; ss = fmaf(v, v, ss);
        }
        atomicAdd(&g_sum[zo + tid], s);
        atomicAdd(&g_sumsq[zo + tid], ss);
    }

    // ---- write y (coalesced) ----
    float* yb = g_y + (size_t)b * COUT * NN + (size_t)zo * NN + n0;
    for (int i = tid; i < 96 * 64; i += 128) {
        int rr = i >> 6, cc = i & 63;
        yb[rr * NN + cc] = ys[rr * 65 + cc];
    }
}

// ---------------------------------------------------------------------------
// Kernel 4: BN apply (scale/shift computed inline from stats) + exact GELU
// ---------------------------------------------------------------------------
__global__ __launch_bounds__(256)
void bn_gelu_kernel(float* __restrict__ out,
                    const float* __restrict__ gamma,
                    const float* __restrict__ beta)
{
    const int i4 = blockIdx.x * blockDim.x + threadIdx.x;
    const int total4 = BB * COUT * NN / 4;
    if (i4 >= total4) return;
    const int ch = (i4 / (NN / 4)) % COUT;
    const float cnt = (float)(BB * NN);
    const float mean = g_sum[ch] / cnt;
    const float var  = g_sumsq[ch] / cnt - mean * mean;
    const float a    = gamma[ch] * rsqrtf(var + 1e-5f);
    const float sh   = beta[ch] - mean * a;
    float4 v = ((const float4*)g_y)[i4];
    v.x = v.x * a + sh;  v.x = v.x * normcdff(v.x);
    v.y = v.y * a + sh;  v.y = v.y * normcdff(v.y);
    v.z = v.z * a + sh;  v.z = v.z * normcdff(v.z);
    v.w = v.w * a + sh;  v.w = v.w * normcdff(v.w);
    ((float4*)out)[i4] = v;
}

// ---------------------------------------------------------------------------
extern "C" void kernel_launch(void* const* d_in, const int* in_sizes, int n_in,
                              void* d_out, int out_size)
{
    const float* x     = (const float*)d_in[0];
    const float* w     = (const float*)d_in[1];
    const float* cbias = (const float*)d_in[2];
    const float* gamma = (const float*)d_in[3];
    const float* beta  = (const float*)d_in[4];
    float* out = (float*)d_out;

    cudaFuncSetAttribute(attn_kernel, cudaFuncAttributeMaxDynamicSharedMemorySize, ATT_SMEM);
    cudaFuncSetAttribute(conv_kernel, cudaFuncAttributeMaxDynamicSharedMemorySize, CV_SMEM);

    prep_kernel<<<dim3((NN + 255) / 256, BB), 256>>>(x);
    wprep_kernel<<<(COUT * 2 * CC + 255) / 256, 256>>>(w);
    attn_kernel<<<dim3(NTILE, BB, KSPLIT), 128, ATT_SMEM>>>();
    attn_fin_kernel<<<(BB * CC * NN / 4 + 255) / 256, 256>>>(x);
    conv_kernel<<<dim3(NTILE, BB, 2), 128, CV_SMEM>>>(cbias);
    bn_gelu_kernel<<<(BB * COUT * NN / 4 + 255) / 256, 256>>>(out, gamma, beta);
}